// round 10
// baseline (speedup 1.0000x reference)
#include <cuda_runtime.h>
#include <cuda_fp16.h>
#include <math.h>
#include <stdint.h>

#define NB 32
#define NN 512
#define ND 768
#define NL 4
#define FS ((size_t)NB * NN * ND)
#define AS ((size_t)NB * NN * NN)
#define DD ((size_t)ND * ND)
#define SCALE_LOGIT 0.03608439182435161f

// GEMM tiling: 128x128x32 tile, 128 threads (4 warps, 64x64 warp tile), 3-stage, 2 CTAs/SM
#define BM 128
#define BN 128
#define BK 32
#define PP 40
#define SM_A 0
#define SM_B (BM * PP)
#define SM_STAGE ((BM + BN) * PP)        // 10240 halves = 20480 B
#define SMEM_BYTES (3 * SM_STAGE * 2)    // 61440 B

// ---------------- static device scratch ----------------
__device__ __align__(16) float g_F[NL][NB * NN * ND];
__device__ __align__(16) float g_adj[NL][NB * NN * NN];
__device__ __align__(16) __half g_Fp[FS];
__device__ __align__(16) __half g_Wq16[NL * DD], g_Wk16[NL * DD];
__device__ __align__(16) __half g_Mt[NL * DD];
__device__ __align__(16) __half g_Ft[NB * ND * NN];
__device__ __align__(16) __half g_aT[NB * NN * NN];
__device__ float g_deg[NL][NB * NN];
__device__ float g_psum[NB];
__device__ float g_fullsum, g_l0, g_cacc[NB * NL], g_gacc[NB * NL];

__device__ __forceinline__ float deg2dis(float d) {
    return (d > 0.f) ? rsqrtf(fmaxf(d, 1e-12f)) : 0.f;
}

// ---------------- small kernels ----------------
__global__ void k_zero() {
    int i = blockIdx.x * 256 + threadIdx.x;
    if (i < NL * NB * NN) ((float*)g_deg)[i] = 0.f;
    if (blockIdx.x == 0) {
        if (threadIdx.x == 0) { g_l0 = 0.f; g_fullsum = 0.f; }
        if (threadIdx.x < NB * NL) { g_cacc[threadIdx.x] = 0.f; g_gacc[threadIdx.x] = 0.f; }
    }
}

__global__ void k_init(const float* __restrict__ pmask) {
    int b = blockIdx.x;
    float s = 0.f;
    for (int i = threadIdx.x; i < NN; i += 256) s += pmask[b * NN + i];
#pragma unroll
    for (int o = 16; o; o >>= 1) s += __shfl_xor_sync(0xffffffffu, s, o);
    __shared__ float sh[8];
    if ((threadIdx.x & 31) == 0) sh[threadIdx.x >> 5] = s;
    __syncthreads();
    if (threadIdx.x == 0) {
        float t = 0.f;
        for (int w = 0; w < 8; w++) t += sh[w];
        g_psum[b] = t;
        atomicAdd(&g_fullsum, t * t);
    }
}

__global__ void k_cvt3(const float4* __restrict__ f, const float4* __restrict__ wq,
                       const float4* __restrict__ wk, __half2* __restrict__ hf,
                       __half2* __restrict__ hwq, __half2* __restrict__ hwk) {
    const int NF = (int)(FS / 4), NW = (int)(NL * DD / 4);
    int i = blockIdx.x * 256 + threadIdx.x;
    const float4* src;
    __half2* dst;
    int j;
    if (i < NF) { src = f; dst = hf; j = i; }
    else if (i < NF + NW) { src = wq; dst = hwq; j = i - NF; }
    else if (i < NF + 2 * NW) { src = wk; dst = hwk; j = i - NF - NW; }
    else return;
    float4 v = src[j];
    dst[2 * j]     = __floats2half2_rn(v.x, v.y);
    dst[2 * j + 1] = __floats2half2_rn(v.z, v.w);
}

// Ft[b][d][n] = Fp[b][n][d] * dis(deg[layer][b][n])
__global__ void t_ft(const __half* __restrict__ Fp, __half* __restrict__ Ft, int layer) {
    int b = blockIdx.z, d0 = blockIdx.x * 32, n0 = blockIdx.y * 32;
    __shared__ float t[32][33];
    int tx = threadIdx.x, ty = threadIdx.y;
#pragma unroll
    for (int r = 0; r < 32; r += 8) {
        int n = n0 + ty + r;
        float dn = deg2dis(g_deg[layer][b * NN + n]);
        t[ty + r][tx] = __half2float(Fp[(size_t)b * NN * ND + (size_t)n * ND + d0 + tx]) * dn;
    }
    __syncthreads();
#pragma unroll
    for (int r = 0; r < 32; r += 8)
        Ft[(size_t)b * ND * NN + (size_t)(d0 + ty + r) * NN + n0 + tx] = __float2half(t[tx][ty + r]);
}

// ---------------- fp16 NT MMA GEMM, 4 warps, 64x64 warp tile ----------------
__device__ __forceinline__ void mma16816(float* d, const uint32_t* a, uint32_t b0, uint32_t b1) {
    asm volatile(
        "mma.sync.aligned.m16n8k16.row.col.f32.f16.f16.f32 "
        "{%0,%1,%2,%3},{%4,%5,%6,%7},{%8,%9},{%0,%1,%2,%3};\n"
        : "+f"(d[0]), "+f"(d[1]), "+f"(d[2]), "+f"(d[3])
        : "r"(a[0]), "r"(a[1]), "r"(a[2]), "r"(a[3]), "r"(b0), "r"(b1));
}

__device__ __forceinline__ void ldsm4(uint32_t& d0, uint32_t& d1, uint32_t& d2, uint32_t& d3,
                                      uint32_t addr) {
    asm volatile("ldmatrix.sync.aligned.m8n8.x4.shared.b16 {%0,%1,%2,%3}, [%4];\n"
                 : "=r"(d0), "=r"(d1), "=r"(d2), "=r"(d3) : "r"(addr));
}

__device__ __forceinline__ void cpa16(__half* dst, const __half* src) {
    uint32_t d = (uint32_t)__cvta_generic_to_shared(dst);
    asm volatile("cp.async.cg.shared.global [%0], [%1], 16;\n" :: "r"(d), "l"(src));
}

// EPI: 0 = fp16 store, 1 = gate, 2 = prop
template <int EPI>
__global__ void __launch_bounds__(128, 2) k_mma(
    const __half* __restrict__ Ag, const __half* __restrict__ Bg,
    float* __restrict__ C, __half* __restrict__ O,
    int K, int lda, int ldb, int ldc,
    size_t bsA, size_t bsB, size_t bsC, size_t bsO,
    const float* __restrict__ pmask, int layer)
{
    extern __shared__ __align__(16) __half smem[];
    __shared__ float pmr[BM], pmc[BN];
    __shared__ float red[3][4];

    const int bz = blockIdx.z;
    Ag += bz * bsA; Bg += bz * bsB;
    if (C) C += bz * bsC;
    if (O) O += bz * bsO;

    const int tid = threadIdx.x;
    const int m0 = blockIdx.y * BM;
    const int n0 = blockIdx.x * BN;

    if (EPI == 1) {
        pmr[tid] = pmask[bz * NN + m0 + tid];
        pmc[tid] = pmask[bz * NN + n0 + tid];
    }

    auto load_stage = [&](int s, int k0) {
        __half* dst = smem + s * SM_STAGE;
#pragma unroll
        for (int i = 0; i < 4; i++) {
            int q = i * 128 + tid, row = q >> 2, c = q & 3;
            cpa16(dst + SM_A + row * PP + c * 8, Ag + (size_t)(m0 + row) * lda + k0 + c * 8);
        }
#pragma unroll
        for (int i = 0; i < 4; i++) {
            int q = i * 128 + tid, row = q >> 2, c = q & 3;
            cpa16(dst + SM_B + row * PP + c * 8, Bg + (size_t)(n0 + row) * ldb + k0 + c * 8);
        }
        asm volatile("cp.async.commit_group;\n");
    };

    float acc[4][8][4];
#pragma unroll
    for (int mi = 0; mi < 4; mi++)
#pragma unroll
        for (int nj = 0; nj < 8; nj++)
#pragma unroll
            for (int q = 0; q < 4; q++) acc[mi][nj][q] = 0.f;

    const int lane = tid & 31;
    const int wid = tid >> 5;
    const int g = lane >> 2, t4 = lane & 3;
    const int wr = (wid & 1) * 64;   // 2 warp-rows x 64
    const int wc = (wid >> 1) * 64;  // 2 warp-cols x 64

    const uint32_t smem32 = (uint32_t)__cvta_generic_to_shared(smem);
    const int aRow = wr + (lane & 15);
    const int aKof = (lane >> 4) << 3;
    const int bRow = wc + (lane & 7) + ((lane >> 4) << 3);
    const int bKof = ((lane >> 3) & 1) << 3;

    const int KT = K / BK;
    load_stage(0, 0);
    load_stage(1, BK);

    for (int kt = 0; kt < KT; kt++) {
        int s = kt % 3;
        if (kt + 1 < KT) {
            asm volatile("cp.async.wait_group 1;\n");
        } else {
            asm volatile("cp.async.wait_group 0;\n");
        }
        __syncthreads();
        if (kt + 2 < KT) load_stage((kt + 2) % 3, (kt + 2) * BK);

        const uint32_t sA32 = smem32 + (s * SM_STAGE + SM_A) * 2;
        const uint32_t sB32 = smem32 + (s * SM_STAGE + SM_B) * 2;

#pragma unroll
        for (int kk = 0; kk < BK; kk += 16) {
            uint32_t af[4][4], bf[8][2];
#pragma unroll
            for (int mi = 0; mi < 4; mi++)
                ldsm4(af[mi][0], af[mi][1], af[mi][2], af[mi][3],
                      sA32 + ((aRow + 16 * mi) * PP + kk + aKof) * 2);
#pragma unroll
            for (int j = 0; j < 4; j++)
                ldsm4(bf[2 * j][0], bf[2 * j][1], bf[2 * j + 1][0], bf[2 * j + 1][1],
                      sB32 + ((bRow + 16 * j) * PP + kk + bKof) * 2);
#pragma unroll
            for (int nj = 0; nj < 8; nj++)
#pragma unroll
                for (int mi = 0; mi < 4; mi++)
                    mma16816(acc[mi][nj], af[mi], bf[nj][0], bf[nj][1]);
        }
    }

    // ---------------- epilogues ----------------
    if (EPI == 0) {
#pragma unroll
        for (int mi = 0; mi < 4; mi++) {
            const int R = m0 + wr + 16 * mi + g;
#pragma unroll
            for (int nj = 0; nj < 8; nj++) {
                const int Cc = n0 + wc + 8 * nj + 2 * t4;
                *(__half2*)(O + (size_t)R * ldc + Cc) =
                    __floats2half2_rn(acc[mi][nj][0], acc[mi][nj][1]);
                *(__half2*)(O + (size_t)(R + 8) * ldc + Cc) =
                    __floats2half2_rn(acc[mi][nj][2], acc[mi][nj][3]);
            }
        }
    } else if (EPI == 2) {
#pragma unroll
        for (int mi = 0; mi < 4; mi++) {
            const int R = m0 + wr + 16 * mi + g;
            const float s1 = deg2dis(g_deg[layer][bz * NN + R]);
            const float s2 = deg2dis(g_deg[layer][bz * NN + R + 8]);
#pragma unroll
            for (int nj = 0; nj < 8; nj++) {
                const int Cc = n0 + wc + 8 * nj + 2 * t4;
                float v0 = acc[mi][nj][0] * s1, v1 = acc[mi][nj][1] * s1;
                float v2 = acc[mi][nj][2] * s2, v3 = acc[mi][nj][3] * s2;
                size_t i1 = (size_t)R * ldc + Cc, i2 = (size_t)(R + 8) * ldc + Cc;
                *(float2*)(C + i1) = make_float2(v0, v1);
                *(float2*)(C + i2) = make_float2(v2, v3);
                *(__half2*)(O + i1) = __floats2half2_rn(v0, v1);
                *(__half2*)(O + i2) = __floats2half2_rn(v2, v3);
            }
        }
    } else {  // gate
        float l0loc = 0.f, cloc = 0.f, gloc = 0.f;
#pragma unroll
        for (int mi = 0; mi < 4; mi++) {
            const int Rl = wr + 16 * mi + g;
            const int R = m0 + Rl;
            const float pr1 = pmr[Rl], pr2 = pmr[Rl + 8];
            float row1 = 0.f, row2 = 0.f;
#pragma unroll
            for (int nj = 0; nj < 8; nj++) {
                const int Ccl = wc + 8 * nj + 2 * t4;
                const int Cc = n0 + Ccl;
                const float pc0 = pmc[Ccl], pc1 = pmc[Ccl + 1];
                float v00 = (1.f / (1.f + expf(-acc[mi][nj][0] * SCALE_LOGIT))) * pr1 * pc0;
                float v01 = (1.f / (1.f + expf(-acc[mi][nj][1] * SCALE_LOGIT))) * pr1 * pc1;
                float v10 = (1.f / (1.f + expf(-acc[mi][nj][2] * SCALE_LOGIT))) * pr2 * pc0;
                float v11 = (1.f / (1.f + expf(-acc[mi][nj][3] * SCALE_LOGIT))) * pr2 * pc1;
                row1 += v00 + v01;
                row2 += v10 + v11;
                l0loc += v00 + v01 + v10 + v11;
                const bool c0ok = (Cc < NN - 1), c1ok = (Cc + 1 < NN - 1);
                float e1 = (c0ok ? v00 : 0.f) + (c1ok ? v01 : 0.f);
                float e2 = (c0ok ? v10 : 0.f) + (c1ok ? v11 : 0.f);
                if (R == NN - 1) cloc += e1; else gloc += e1;
                if (R + 8 == NN - 1) cloc += e2; else gloc += e2;
                *(float2*)(C + (size_t)R * ldc + Cc) = make_float2(v00, v01);
                *(float2*)(C + (size_t)(R + 8) * ldc + Cc) = make_float2(v10, v11);
                O[(size_t)Cc * NN + R]           = __float2half(v00);
                O[(size_t)(Cc + 1) * NN + R]     = __float2half(v01);
                O[(size_t)Cc * NN + R + 8]       = __float2half(v10);
                O[(size_t)(Cc + 1) * NN + R + 8] = __float2half(v11);
            }
            row1 += __shfl_xor_sync(0xffffffffu, row1, 1);
            row1 += __shfl_xor_sync(0xffffffffu, row1, 2);
            row2 += __shfl_xor_sync(0xffffffffu, row2, 1);
            row2 += __shfl_xor_sync(0xffffffffu, row2, 2);
            if (t4 == 0) {
                atomicAdd(&g_deg[layer][bz * NN + R], row1);
                atomicAdd(&g_deg[layer][bz * NN + R + 8], row2);
            }
        }
#pragma unroll
        for (int o = 16; o; o >>= 1) {
            l0loc += __shfl_xor_sync(0xffffffffu, l0loc, o);
            cloc  += __shfl_xor_sync(0xffffffffu, cloc, o);
            gloc  += __shfl_xor_sync(0xffffffffu, gloc, o);
        }
        if (lane == 0) { red[0][wid] = l0loc; red[1][wid] = cloc; red[2][wid] = gloc; }
        __syncthreads();
        if (tid == 0) {
            float a = 0.f, c = 0.f, gg = 0.f;
            for (int w = 0; w < 4; w++) { a += red[0][w]; c += red[1][w]; gg += red[2][w]; }
            atomicAdd(&g_l0, a);
            atomicAdd(&g_cacc[bz * NL + layer], c);
            atomicAdd(&g_gacc[bz * NL + layer], gg);
        }
    }
}

// ---------------- attention-pool epilogue ----------------
__global__ void __launch_bounds__(256) k_final(
    const float* __restrict__ F0, const float* __restrict__ projw,
    const float* __restrict__ projb, float* __restrict__ out, float* __restrict__ retain)
{
    const int bn = blockIdx.x;
    const float* p0 = F0 + (size_t)bn * ND;
    const float* p1 = g_F[0] + (size_t)bn * ND;
    const float* p2 = g_F[1] + (size_t)bn * ND;
    const float* p3 = g_F[2] + (size_t)bn * ND;
    const float* p4 = g_F[3] + (size_t)bn * ND;
    float d0 = 0.f, d1 = 0.f, d2 = 0.f, d3 = 0.f, d4 = 0.f;
    for (int i = threadIdx.x; i < ND; i += 256) {
        float w = projw[i];
        d0 += p0[i] * w; d1 += p1[i] * w; d2 += p2[i] * w; d3 += p3[i] * w; d4 += p4[i] * w;
    }
#pragma unroll
    for (int o = 16; o; o >>= 1) {
        d0 += __shfl_xor_sync(0xffffffffu, d0, o);
        d1 += __shfl_xor_sync(0xffffffffu, d1, o);
        d2 += __shfl_xor_sync(0xffffffffu, d2, o);
        d3 += __shfl_xor_sync(0xffffffffu, d3, o);
        d4 += __shfl_xor_sync(0xffffffffu, d4, o);
    }
    __shared__ float sh[5][8], r[5];
    const int wid = threadIdx.x >> 5, lane = threadIdx.x & 31;
    if (lane == 0) { sh[0][wid] = d0; sh[1][wid] = d1; sh[2][wid] = d2; sh[3][wid] = d3; sh[4][wid] = d4; }
    __syncthreads();
    if (threadIdx.x < 5) {
        float t = 0.f;
        for (int w = 0; w < 8; w++) t += sh[threadIdx.x][w];
        float rr = 1.f / (1.f + expf(-(t + projb[0])));
        r[threadIdx.x] = rr;
        retain[(size_t)bn * (NL + 1) + threadIdx.x] = rr;
    }
    __syncthreads();
    const float r0 = r[0], r1 = r[1], r2 = r[2], r3 = r[3], r4 = r[4];
    for (int i = threadIdx.x; i < ND; i += 256)
        out[(size_t)bn * ND + i] = r0 * p0[i] + r1 * p1[i] + r2 * p2[i] + r3 * p3[i] + r4 * p4[i];
}

__global__ void k_repack(float* __restrict__ adjs_out) {
    size_t i = (size_t)blockIdx.x * 256 + threadIdx.x;
    ((float4*)adjs_out)[i] = make_float4(g_adj[0][i], g_adj[1][i], g_adj[2][i], g_adj[3][i]);
}

__global__ void k_finalize(float* __restrict__ o_l0, float* __restrict__ o_c, float* __restrict__ o_g) {
    int t = threadIdx.x;
    if (t == 0) *o_l0 = g_l0 / ((g_fullsum + 1e-8f) * (float)NL);
    if (t < NB * NL) {
        int b = t / NL;
        float ps = g_psum[b];
        o_c[t] = g_cacc[t] / ps;
        o_g[t] = g_gacc[t] / (ps * ps);
    }
}

// ---------------- host orchestration ----------------
extern "C" void kernel_launch(void* const* d_in, const int* in_sizes, int n_in,
                              void* d_out, int out_size)
{
    (void)in_sizes; (void)n_in; (void)out_size;
    const float* pmask   = (const float*)d_in[0];
    const float* feature = (const float*)d_in[1];
    const float* Wq      = (const float*)d_in[2];
    const float* Wk      = (const float*)d_in[3];
    const float* projw   = (const float*)d_in[4];
    const float* projb   = (const float*)d_in[5];

    float* out    = (float*)d_out;
    float* retain = out + FS;
    float* adjs   = retain + (size_t)NB * NN * (NL + 1);
    float* o_l0   = adjs + AS * NL;
    float* o_c    = o_l0 + 1;
    float* o_g    = o_c + NB * NL;

    cudaFuncSetAttribute((const void*)&k_mma<0>, cudaFuncAttributeMaxDynamicSharedMemorySize, SMEM_BYTES);
    cudaFuncSetAttribute((const void*)&k_mma<1>, cudaFuncAttributeMaxDynamicSharedMemorySize, SMEM_BYTES);
    cudaFuncSetAttribute((const void*)&k_mma<2>, cudaFuncAttributeMaxDynamicSharedMemorySize, SMEM_BYTES);

    float *pF, *pAdj;
    __half *pFp, *pWq16, *pWk16, *pMt, *pFt, *paT;
    cudaGetSymbolAddress((void**)&pF, g_F);
    cudaGetSymbolAddress((void**)&pAdj, g_adj);
    cudaGetSymbolAddress((void**)&pFp, g_Fp);
    cudaGetSymbolAddress((void**)&pWq16, g_Wq16);
    cudaGetSymbolAddress((void**)&pWk16, g_Wk16);
    cudaGetSymbolAddress((void**)&pMt, g_Mt);
    cudaGetSymbolAddress((void**)&pFt, g_Ft);
    cudaGetSymbolAddress((void**)&paT, g_aT);

    k_zero<<<256, 256>>>();
    k_init<<<NB, 256>>>(pmask);
    {
        int total = (int)(FS / 4) + 2 * (int)(NL * DD / 4);
        k_cvt3<<<(total + 255) / 256, 256>>>(
            (const float4*)feature, (const float4*)Wq, (const float4*)Wk,
            (__half2*)pFp, (__half2*)pWq16, (__half2*)pWk16);
    }

    // Mt[l] = Wk[l] * Wq[l]^T (fp16), batched over layers
    k_mma<0><<<dim3(ND / BN, ND / BM, NL), 128, SMEM_BYTES>>>(
        pWk16, pWq16, nullptr, pMt, ND, ND, ND, ND, DD, DD, 0, DD, nullptr, 0);

    for (int l = 0; l < NL; l++) {
        // G = F * Mt[l]^T (fp16 into g_Ft scratch)
        k_mma<0><<<dim3(ND / BN, (NB * NN) / BM, 1), 128, SMEM_BYTES>>>(
            pFp, pMt + (size_t)l * DD, nullptr, pFt,
            ND, ND, ND, ND, 0, 0, 0, 0, nullptr, 0);
        // adj = sigmoid(scale * G F^T) * mask (+deg/c/g/l0 + adjT fp16)
        k_mma<1><<<dim3(NN / BN, NN / BM, NB), 128, SMEM_BYTES>>>(
            pFt, pFp, pAdj + (size_t)l * AS, paT,
            ND, ND, ND, NN,
            (size_t)NN * ND, (size_t)NN * ND, (size_t)NN * NN, (size_t)NN * NN, pmask, l);
        // Ft = (F * dis[n])^T fp16 (overwrites G scratch)
        t_ft<<<dim3(ND / 32, NN / 32, NB), dim3(32, 8)>>>(pFp, pFt, l);
        // Fout[m,d] = dis[m] * sum_n adjT[m,n]*Ft[d,n]
        k_mma<2><<<dim3(ND / BN, NN / BM, NB), 128, SMEM_BYTES>>>(
            paT, pFt, pF + (size_t)l * FS, pFp,
            NN, NN, NN, ND,
            (size_t)NN * NN, (size_t)ND * NN, (size_t)NN * ND, (size_t)NN * ND, nullptr, l);
    }

    k_final<<<NB * NN, 256>>>(feature, projw, projb, out, retain);
    k_repack<<<(int)(AS / 256), 256>>>(adjs);
    k_finalize<<<1, 128>>>(o_l0, o_c, o_g);
}

// round 11
// speedup vs baseline: 1.1069x; 1.1069x over previous
#include <cuda_runtime.h>
#include <cuda_fp16.h>
#include <math.h>
#include <stdint.h>

#define NB 32
#define NN 512
#define ND 768
#define NL 4
#define FS ((size_t)NB * NN * ND)
#define AS ((size_t)NB * NN * NN)
#define DD ((size_t)ND * ND)
#define SCALE_LOGIT 0.03608439182435161f

// GEMM tiling: 128x128x64 tile, 256 threads (8 warps, 32x64 warp tile), 3-stage, 2 CTAs/SM
#define BM 128
#define BN 128
#define BK 64
#define PP 72
#define SM_A 0
#define SM_B (BM * PP)
#define SM_STAGE ((BM + BN) * PP)        // 18432 halves = 36864 B
#define SMEM_BYTES (3 * SM_STAGE * 2)    // 110592 B

// ---------------- static device scratch ----------------
__device__ __align__(16) float g_F[NL][NB * NN * ND];
__device__ __align__(16) float g_adj[NL][NB * NN * NN];
__device__ __align__(16) __half g_Fp[FS];
__device__ __align__(16) __half g_Wq16[NL * DD], g_Wk16[NL * DD];
__device__ __align__(16) __half g_Mt[NL * DD];
__device__ __align__(16) __half g_Ft[NB * ND * NN];
__device__ __align__(16) __half g_aT[NB * NN * NN];
__device__ float g_deg[NL][NB * NN];
__device__ float g_psum[NB];
__device__ float g_fullsum, g_l0, g_cacc[NB * NL], g_gacc[NB * NL];

__device__ __forceinline__ float deg2dis(float d) {
    return (d > 0.f) ? rsqrtf(fmaxf(d, 1e-12f)) : 0.f;
}

// ---------------- small kernels ----------------
__global__ void k_zero() {
    int i = blockIdx.x * 256 + threadIdx.x;
    if (i < NL * NB * NN) ((float*)g_deg)[i] = 0.f;
    if (blockIdx.x == 0) {
        if (threadIdx.x == 0) { g_l0 = 0.f; g_fullsum = 0.f; }
        if (threadIdx.x < NB * NL) { g_cacc[threadIdx.x] = 0.f; g_gacc[threadIdx.x] = 0.f; }
    }
}

__global__ void k_init(const float* __restrict__ pmask) {
    int b = blockIdx.x;
    float s = 0.f;
    for (int i = threadIdx.x; i < NN; i += 256) s += pmask[b * NN + i];
#pragma unroll
    for (int o = 16; o; o >>= 1) s += __shfl_xor_sync(0xffffffffu, s, o);
    __shared__ float sh[8];
    if ((threadIdx.x & 31) == 0) sh[threadIdx.x >> 5] = s;
    __syncthreads();
    if (threadIdx.x == 0) {
        float t = 0.f;
        for (int w = 0; w < 8; w++) t += sh[w];
        g_psum[b] = t;
        atomicAdd(&g_fullsum, t * t);
    }
}

__global__ void k_cvt3(const float4* __restrict__ f, const float4* __restrict__ wq,
                       const float4* __restrict__ wk, __half2* __restrict__ hf,
                       __half2* __restrict__ hwq, __half2* __restrict__ hwk) {
    const int NF = (int)(FS / 4), NW = (int)(NL * DD / 4);
    int i = blockIdx.x * 256 + threadIdx.x;
    const float4* src;
    __half2* dst;
    int j;
    if (i < NF) { src = f; dst = hf; j = i; }
    else if (i < NF + NW) { src = wq; dst = hwq; j = i - NF; }
    else if (i < NF + 2 * NW) { src = wk; dst = hwk; j = i - NF - NW; }
    else return;
    float4 v = src[j];
    dst[2 * j]     = __floats2half2_rn(v.x, v.y);
    dst[2 * j + 1] = __floats2half2_rn(v.z, v.w);
}

// Ft[b][d][n] = Fp[b][n][d] * dis(deg[layer][b][n])
__global__ void t_ft(const __half* __restrict__ Fp, __half* __restrict__ Ft, int layer) {
    int b = blockIdx.z, d0 = blockIdx.x * 32, n0 = blockIdx.y * 32;
    __shared__ float t[32][33];
    int tx = threadIdx.x, ty = threadIdx.y;
#pragma unroll
    for (int r = 0; r < 32; r += 8) {
        int n = n0 + ty + r;
        float dn = deg2dis(g_deg[layer][b * NN + n]);
        t[ty + r][tx] = __half2float(Fp[(size_t)b * NN * ND + (size_t)n * ND + d0 + tx]) * dn;
    }
    __syncthreads();
#pragma unroll
    for (int r = 0; r < 32; r += 8)
        Ft[(size_t)b * ND * NN + (size_t)(d0 + ty + r) * NN + n0 + tx] = __float2half(t[tx][ty + r]);
}

// ---------------- fp16 NT MMA GEMM, BK=64, 3-stage, 2 CTAs/SM ----------------
__device__ __forceinline__ void mma16816(float* d, const uint32_t* a, uint32_t b0, uint32_t b1) {
    asm volatile(
        "mma.sync.aligned.m16n8k16.row.col.f32.f16.f16.f32 "
        "{%0,%1,%2,%3},{%4,%5,%6,%7},{%8,%9},{%0,%1,%2,%3};\n"
        : "+f"(d[0]), "+f"(d[1]), "+f"(d[2]), "+f"(d[3])
        : "r"(a[0]), "r"(a[1]), "r"(a[2]), "r"(a[3]), "r"(b0), "r"(b1));
}

__device__ __forceinline__ void ldsm4(uint32_t& d0, uint32_t& d1, uint32_t& d2, uint32_t& d3,
                                      uint32_t addr) {
    asm volatile("ldmatrix.sync.aligned.m8n8.x4.shared.b16 {%0,%1,%2,%3}, [%4];\n"
                 : "=r"(d0), "=r"(d1), "=r"(d2), "=r"(d3) : "r"(addr));
}

__device__ __forceinline__ void cpa16(__half* dst, const __half* src) {
    uint32_t d = (uint32_t)__cvta_generic_to_shared(dst);
    asm volatile("cp.async.cg.shared.global [%0], [%1], 16;\n" :: "r"(d), "l"(src));
}

// EPI: 0 = fp16 store, 1 = gate, 2 = prop
template <int EPI>
__global__ void __launch_bounds__(256, 2) k_mma(
    const __half* __restrict__ Ag, const __half* __restrict__ Bg,
    float* __restrict__ C, __half* __restrict__ O,
    int K, int lda, int ldb, int ldc,
    size_t bsA, size_t bsB, size_t bsC, size_t bsO,
    const float* __restrict__ pmask, int layer)
{
    extern __shared__ __align__(16) __half smem[];
    __shared__ float pmr[BM], pmc[BN];
    __shared__ float red[3][8];

    const int bz = blockIdx.z;
    Ag += bz * bsA; Bg += bz * bsB;
    if (C) C += bz * bsC;
    if (O) O += bz * bsO;

    const int tid = threadIdx.x;
    const int m0 = blockIdx.y * BM;
    const int n0 = blockIdx.x * BN;

    if (EPI == 1) {
        if (tid < BM) pmr[tid] = pmask[bz * NN + m0 + tid];
        else          pmc[tid - BM] = pmask[bz * NN + n0 + (tid - BM)];
    }

    auto load_stage = [&](int s, int k0) {
        __half* dst = smem + s * SM_STAGE;
#pragma unroll
        for (int i = 0; i < 4; i++) {
            int q = i * 256 + tid, row = q >> 3, c = q & 7;
            cpa16(dst + SM_A + row * PP + c * 8, Ag + (size_t)(m0 + row) * lda + k0 + c * 8);
        }
#pragma unroll
        for (int i = 0; i < 4; i++) {
            int q = i * 256 + tid, row = q >> 3, c = q & 7;
            cpa16(dst + SM_B + row * PP + c * 8, Bg + (size_t)(n0 + row) * ldb + k0 + c * 8);
        }
        asm volatile("cp.async.commit_group;\n");
    };

    float acc[2][8][4];
#pragma unroll
    for (int mi = 0; mi < 2; mi++)
#pragma unroll
        for (int nj = 0; nj < 8; nj++)
#pragma unroll
            for (int q = 0; q < 4; q++) acc[mi][nj][q] = 0.f;

    const int lane = tid & 31;
    const int wid = tid >> 5;
    const int g = lane >> 2, t4 = lane & 3;
    const int wr = (wid & 3) * 32;
    const int wc = (wid >> 2) * 64;

    const uint32_t smem32 = (uint32_t)__cvta_generic_to_shared(smem);
    const int aRow = wr + (lane & 15);
    const int aKof = (lane >> 4) << 3;
    const int bRow = wc + (lane & 7) + ((lane >> 4) << 3);
    const int bKof = ((lane >> 3) & 1) << 3;

    const int KT = K / BK;
    load_stage(0, 0);
    load_stage(1, BK);

    for (int kt = 0; kt < KT; kt++) {
        int s = kt % 3;
        if (kt + 1 < KT) {
            asm volatile("cp.async.wait_group 1;\n");
        } else {
            asm volatile("cp.async.wait_group 0;\n");
        }
        __syncthreads();
        if (kt + 2 < KT) load_stage((kt + 2) % 3, (kt + 2) * BK);

        const uint32_t sA32 = smem32 + (s * SM_STAGE + SM_A) * 2;
        const uint32_t sB32 = smem32 + (s * SM_STAGE + SM_B) * 2;

#pragma unroll
        for (int kk = 0; kk < BK; kk += 16) {
            uint32_t af[2][4], bf[8][2];
#pragma unroll
            for (int mi = 0; mi < 2; mi++)
                ldsm4(af[mi][0], af[mi][1], af[mi][2], af[mi][3],
                      sA32 + ((aRow + 16 * mi) * PP + kk + aKof) * 2);
#pragma unroll
            for (int j = 0; j < 4; j++)
                ldsm4(bf[2 * j][0], bf[2 * j][1], bf[2 * j + 1][0], bf[2 * j + 1][1],
                      sB32 + ((bRow + 16 * j) * PP + kk + bKof) * 2);
#pragma unroll
            for (int nj = 0; nj < 8; nj++)
#pragma unroll
                for (int mi = 0; mi < 2; mi++)
                    mma16816(acc[mi][nj], af[mi], bf[nj][0], bf[nj][1]);
        }
    }

    // ---------------- epilogues ----------------
    if (EPI == 0) {
#pragma unroll
        for (int mi = 0; mi < 2; mi++) {
            const int R = m0 + wr + 16 * mi + g;
#pragma unroll
            for (int nj = 0; nj < 8; nj++) {
                const int Cc = n0 + wc + 8 * nj + 2 * t4;
                *(__half2*)(O + (size_t)R * ldc + Cc) =
                    __floats2half2_rn(acc[mi][nj][0], acc[mi][nj][1]);
                *(__half2*)(O + (size_t)(R + 8) * ldc + Cc) =
                    __floats2half2_rn(acc[mi][nj][2], acc[mi][nj][3]);
            }
        }
    } else if (EPI == 2) {
#pragma unroll
        for (int mi = 0; mi < 2; mi++) {
            const int R = m0 + wr + 16 * mi + g;
            const float s1 = deg2dis(g_deg[layer][bz * NN + R]);
            const float s2 = deg2dis(g_deg[layer][bz * NN + R + 8]);
#pragma unroll
            for (int nj = 0; nj < 8; nj++) {
                const int Cc = n0 + wc + 8 * nj + 2 * t4;
                float v0 = acc[mi][nj][0] * s1, v1 = acc[mi][nj][1] * s1;
                float v2 = acc[mi][nj][2] * s2, v3 = acc[mi][nj][3] * s2;
                size_t i1 = (size_t)R * ldc + Cc, i2 = (size_t)(R + 8) * ldc + Cc;
                *(float2*)(C + i1) = make_float2(v0, v1);
                *(float2*)(C + i2) = make_float2(v2, v3);
                *(__half2*)(O + i1) = __floats2half2_rn(v0, v1);
                *(__half2*)(O + i2) = __floats2half2_rn(v2, v3);
            }
        }
    } else {  // gate
        float l0loc = 0.f, cloc = 0.f, gloc = 0.f;
#pragma unroll
        for (int mi = 0; mi < 2; mi++) {
            const int Rl = wr + 16 * mi + g;
            const int R = m0 + Rl;
            const float pr1 = pmr[Rl], pr2 = pmr[Rl + 8];
            float row1 = 0.f, row2 = 0.f;
#pragma unroll
            for (int nj = 0; nj < 8; nj++) {
                const int Ccl = wc + 8 * nj + 2 * t4;
                const int Cc = n0 + Ccl;
                const float pc0 = pmc[Ccl], pc1 = pmc[Ccl + 1];
                float v00 = (1.f / (1.f + expf(-acc[mi][nj][0] * SCALE_LOGIT))) * pr1 * pc0;
                float v01 = (1.f / (1.f + expf(-acc[mi][nj][1] * SCALE_LOGIT))) * pr1 * pc1;
                float v10 = (1.f / (1.f + expf(-acc[mi][nj][2] * SCALE_LOGIT))) * pr2 * pc0;
                float v11 = (1.f / (1.f + expf(-acc[mi][nj][3] * SCALE_LOGIT))) * pr2 * pc1;
                row1 += v00 + v01;
                row2 += v10 + v11;
                l0loc += v00 + v01 + v10 + v11;
                const bool c0ok = (Cc < NN - 1), c1ok = (Cc + 1 < NN - 1);
                float e1 = (c0ok ? v00 : 0.f) + (c1ok ? v01 : 0.f);
                float e2 = (c0ok ? v10 : 0.f) + (c1ok ? v11 : 0.f);
                if (R == NN - 1) cloc += e1; else gloc += e1;
                if (R + 8 == NN - 1) cloc += e2; else gloc += e2;
                *(float2*)(C + (size_t)R * ldc + Cc) = make_float2(v00, v01);
                *(float2*)(C + (size_t)(R + 8) * ldc + Cc) = make_float2(v10, v11);
                O[(size_t)Cc * NN + R]           = __float2half(v00);
                O[(size_t)(Cc + 1) * NN + R]     = __float2half(v01);
                O[(size_t)Cc * NN + R + 8]       = __float2half(v10);
                O[(size_t)(Cc + 1) * NN + R + 8] = __float2half(v11);
            }
            row1 += __shfl_xor_sync(0xffffffffu, row1, 1);
            row1 += __shfl_xor_sync(0xffffffffu, row1, 2);
            row2 += __shfl_xor_sync(0xffffffffu, row2, 1);
            row2 += __shfl_xor_sync(0xffffffffu, row2, 2);
            if (t4 == 0) {
                atomicAdd(&g_deg[layer][bz * NN + R], row1);
                atomicAdd(&g_deg[layer][bz * NN + R + 8], row2);
            }
        }
#pragma unroll
        for (int o = 16; o; o >>= 1) {
            l0loc += __shfl_xor_sync(0xffffffffu, l0loc, o);
            cloc  += __shfl_xor_sync(0xffffffffu, cloc, o);
            gloc  += __shfl_xor_sync(0xffffffffu, gloc, o);
        }
        if (lane == 0) { red[0][wid] = l0loc; red[1][wid] = cloc; red[2][wid] = gloc; }
        __syncthreads();
        if (tid == 0) {
            float a = 0.f, c = 0.f, gg = 0.f;
            for (int w = 0; w < 8; w++) { a += red[0][w]; c += red[1][w]; gg += red[2][w]; }
            atomicAdd(&g_l0, a);
            atomicAdd(&g_cacc[bz * NL + layer], c);
            atomicAdd(&g_gacc[bz * NL + layer], gg);
        }
    }
}

// ---------------- attention-pool epilogue ----------------
__global__ void __launch_bounds__(256) k_final(
    const float* __restrict__ F0, const float* __restrict__ projw,
    const float* __restrict__ projb, float* __restrict__ out, float* __restrict__ retain)
{
    const int bn = blockIdx.x;
    const float* p0 = F0 + (size_t)bn * ND;
    const float* p1 = g_F[0] + (size_t)bn * ND;
    const float* p2 = g_F[1] + (size_t)bn * ND;
    const float* p3 = g_F[2] + (size_t)bn * ND;
    const float* p4 = g_F[3] + (size_t)bn * ND;
    float d0 = 0.f, d1 = 0.f, d2 = 0.f, d3 = 0.f, d4 = 0.f;
    for (int i = threadIdx.x; i < ND; i += 256) {
        float w = projw[i];
        d0 += p0[i] * w; d1 += p1[i] * w; d2 += p2[i] * w; d3 += p3[i] * w; d4 += p4[i] * w;
    }
#pragma unroll
    for (int o = 16; o; o >>= 1) {
        d0 += __shfl_xor_sync(0xffffffffu, d0, o);
        d1 += __shfl_xor_sync(0xffffffffu, d1, o);
        d2 += __shfl_xor_sync(0xffffffffu, d2, o);
        d3 += __shfl_xor_sync(0xffffffffu, d3, o);
        d4 += __shfl_xor_sync(0xffffffffu, d4, o);
    }
    __shared__ float sh[5][8], r[5];
    const int wid = threadIdx.x >> 5, lane = threadIdx.x & 31;
    if (lane == 0) { sh[0][wid] = d0; sh[1][wid] = d1; sh[2][wid] = d2; sh[3][wid] = d3; sh[4][wid] = d4; }
    __syncthreads();
    if (threadIdx.x < 5) {
        float t = 0.f;
        for (int w = 0; w < 8; w++) t += sh[threadIdx.x][w];
        float rr = 1.f / (1.f + expf(-(t + projb[0])));
        r[threadIdx.x] = rr;
        retain[(size_t)bn * (NL + 1) + threadIdx.x] = rr;
    }
    __syncthreads();
    const float r0 = r[0], r1 = r[1], r2 = r[2], r3 = r[3], r4 = r[4];
    for (int i = threadIdx.x; i < ND; i += 256)
        out[(size_t)bn * ND + i] = r0 * p0[i] + r1 * p1[i] + r2 * p2[i] + r3 * p3[i] + r4 * p4[i];
}

__global__ void k_repack(float* __restrict__ adjs_out) {
    size_t i = (size_t)blockIdx.x * 256 + threadIdx.x;
    ((float4*)adjs_out)[i] = make_float4(g_adj[0][i], g_adj[1][i], g_adj[2][i], g_adj[3][i]);
}

__global__ void k_finalize(float* __restrict__ o_l0, float* __restrict__ o_c, float* __restrict__ o_g) {
    int t = threadIdx.x;
    if (t == 0) *o_l0 = g_l0 / ((g_fullsum + 1e-8f) * (float)NL);
    if (t < NB * NL) {
        int b = t / NL;
        float ps = g_psum[b];
        o_c[t] = g_cacc[t] / ps;
        o_g[t] = g_gacc[t] / (ps * ps);
    }
}

// ---------------- host orchestration ----------------
extern "C" void kernel_launch(void* const* d_in, const int* in_sizes, int n_in,
                              void* d_out, int out_size)
{
    (void)in_sizes; (void)n_in; (void)out_size;
    const float* pmask   = (const float*)d_in[0];
    const float* feature = (const float*)d_in[1];
    const float* Wq      = (const float*)d_in[2];
    const float* Wk      = (const float*)d_in[3];
    const float* projw   = (const float*)d_in[4];
    const float* projb   = (const float*)d_in[5];

    float* out    = (float*)d_out;
    float* retain = out + FS;
    float* adjs   = retain + (size_t)NB * NN * (NL + 1);
    float* o_l0   = adjs + AS * NL;
    float* o_c    = o_l0 + 1;
    float* o_g    = o_c + NB * NL;

    cudaFuncSetAttribute((const void*)&k_mma<0>, cudaFuncAttributeMaxDynamicSharedMemorySize, SMEM_BYTES);
    cudaFuncSetAttribute((const void*)&k_mma<1>, cudaFuncAttributeMaxDynamicSharedMemorySize, SMEM_BYTES);
    cudaFuncSetAttribute((const void*)&k_mma<2>, cudaFuncAttributeMaxDynamicSharedMemorySize, SMEM_BYTES);

    float *pF, *pAdj;
    __half *pFp, *pWq16, *pWk16, *pMt, *pFt, *paT;
    cudaGetSymbolAddress((void**)&pF, g_F);
    cudaGetSymbolAddress((void**)&pAdj, g_adj);
    cudaGetSymbolAddress((void**)&pFp, g_Fp);
    cudaGetSymbolAddress((void**)&pWq16, g_Wq16);
    cudaGetSymbolAddress((void**)&pWk16, g_Wk16);
    cudaGetSymbolAddress((void**)&pMt, g_Mt);
    cudaGetSymbolAddress((void**)&pFt, g_Ft);
    cudaGetSymbolAddress((void**)&paT, g_aT);

    k_zero<<<256, 256>>>();
    k_init<<<NB, 256>>>(pmask);
    {
        int total = (int)(FS / 4) + 2 * (int)(NL * DD / 4);
        k_cvt3<<<(total + 255) / 256, 256>>>(
            (const float4*)feature, (const float4*)Wq, (const float4*)Wk,
            (__half2*)pFp, (__half2*)pWq16, (__half2*)pWk16);
    }

    // Mt[l] = Wk[l] * Wq[l]^T (fp16), batched over layers
    k_mma<0><<<dim3(ND / BN, ND / BM, NL), 256, SMEM_BYTES>>>(
        pWk16, pWq16, nullptr, pMt, ND, ND, ND, ND, DD, DD, 0, DD, nullptr, 0);

    for (int l = 0; l < NL; l++) {
        // G = F * Mt[l]^T (fp16 into g_Ft scratch)
        k_mma<0><<<dim3(ND / BN, (NB * NN) / BM, 1), 256, SMEM_BYTES>>>(
            pFp, pMt + (size_t)l * DD, nullptr, pFt,
            ND, ND, ND, ND, 0, 0, 0, 0, nullptr, 0);
        // adj = sigmoid(scale * G F^T) * mask (+deg/c/g/l0 + adjT fp16)
        k_mma<1><<<dim3(NN / BN, NN / BM, NB), 256, SMEM_BYTES>>>(
            pFt, pFp, pAdj + (size_t)l * AS, paT,
            ND, ND, ND, NN,
            (size_t)NN * ND, (size_t)NN * ND, (size_t)NN * NN, (size_t)NN * NN, pmask, l);
        // Ft = (F * dis[n])^T fp16 (overwrites G scratch)
        t_ft<<<dim3(ND / 32, NN / 32, NB), dim3(32, 8)>>>(pFp, pFt, l);
        // Fout[m,d] = dis[m] * sum_n adjT[m,n]*Ft[d,n]
        k_mma<2><<<dim3(ND / BN, NN / BM, NB), 256, SMEM_BYTES>>>(
            paT, pFt, pF + (size_t)l * FS, pFp,
            NN, NN, NN, ND,
            (size_t)NN * NN, (size_t)ND * NN, (size_t)NN * ND, (size_t)NN * ND, nullptr, l);
    }

    k_final<<<NB * NN, 256>>>(feature, projw, projb, out, retain);
    k_repack<<<(int)(AS / 256), 256>>>(adjs);
    k_finalize<<<1, 128>>>(o_l0, o_c, o_g);
}

// round 12
// speedup vs baseline: 1.1540x; 1.0425x over previous
#include <cuda_runtime.h>
#include <cuda_fp16.h>
#include <math.h>
#include <stdint.h>

#define NB 32
#define NN 512
#define ND 768
#define NL 4
#define FS ((size_t)NB * NN * ND)
#define AS ((size_t)NB * NN * NN)
#define DD ((size_t)ND * ND)
#define SCALE_LOGIT 0.03608439182435161f

// GEMM tiling: 128x128x64 tile, 256 threads (8 warps, 32x64 warp tile), 3-stage, 2 CTAs/SM
#define BM 128
#define BN 128
#define BK 64
#define PP 72
#define SM_A 0
#define SM_B (BM * PP)
#define SM_STAGE ((BM + BN) * PP)        // 18432 halves = 36864 B
#define SMEM_BYTES (3 * SM_STAGE * 2)    // 110592 B

// ---------------- static device scratch ----------------
__device__ __align__(16) float g_adj[NL][NB * NN * NN];
__device__ __align__(16) __half g_F16[NL][NB * NN * ND];  // fp16 features per layer
__device__ __align__(16) __half g_Fp[FS];                 // initial feature fp16
__device__ __align__(16) __half g_Wq16[NL * DD], g_Wk16[NL * DD];
__device__ __align__(16) __half g_Mt[NL * DD];
__device__ __align__(16) __half g_Ft[NB * ND * NN];
__device__ __align__(16) __half g_aT[NB * NN * NN];
__device__ float g_deg[NL][NB * NN];
__device__ float g_psum[NB];
__device__ float g_fullsum, g_l0, g_cacc[NB * NL], g_gacc[NB * NL];

__device__ __forceinline__ float deg2dis(float d) {
    return (d > 0.f) ? rsqrtf(fmaxf(d, 1e-12f)) : 0.f;
}

// ---------------- small kernels ----------------
__global__ void k_zero() {
    int i = blockIdx.x * 256 + threadIdx.x;
    if (i < NL * NB * NN) ((float*)g_deg)[i] = 0.f;
    if (blockIdx.x == 0) {
        if (threadIdx.x == 0) { g_l0 = 0.f; g_fullsum = 0.f; }
        if (threadIdx.x < NB * NL) { g_cacc[threadIdx.x] = 0.f; g_gacc[threadIdx.x] = 0.f; }
    }
}

__global__ void k_init(const float* __restrict__ pmask) {
    int b = blockIdx.x;
    float s = 0.f;
    for (int i = threadIdx.x; i < NN; i += 256) s += pmask[b * NN + i];
#pragma unroll
    for (int o = 16; o; o >>= 1) s += __shfl_xor_sync(0xffffffffu, s, o);
    __shared__ float sh[8];
    if ((threadIdx.x & 31) == 0) sh[threadIdx.x >> 5] = s;
    __syncthreads();
    if (threadIdx.x == 0) {
        float t = 0.f;
        for (int w = 0; w < 8; w++) t += sh[w];
        g_psum[b] = t;
        atomicAdd(&g_fullsum, t * t);
    }
}

__global__ void k_cvt3(const float4* __restrict__ f, const float4* __restrict__ wq,
                       const float4* __restrict__ wk, __half2* __restrict__ hf,
                       __half2* __restrict__ hwq, __half2* __restrict__ hwk) {
    const int NF = (int)(FS / 4), NW = (int)(NL * DD / 4);
    int i = blockIdx.x * 256 + threadIdx.x;
    const float4* src;
    __half2* dst;
    int j;
    if (i < NF) { src = f; dst = hf; j = i; }
    else if (i < NF + NW) { src = wq; dst = hwq; j = i - NF; }
    else if (i < NF + 2 * NW) { src = wk; dst = hwk; j = i - NF - NW; }
    else return;
    float4 v = src[j];
    dst[2 * j]     = __floats2half2_rn(v.x, v.y);
    dst[2 * j + 1] = __floats2half2_rn(v.z, v.w);
}

// Ft[b][d][n] = Fp[b][n][d] * dis(deg[layer][b][n])
__global__ void t_ft(const __half* __restrict__ Fp, __half* __restrict__ Ft, int layer) {
    int b = blockIdx.z, d0 = blockIdx.x * 32, n0 = blockIdx.y * 32;
    __shared__ float t[32][33];
    int tx = threadIdx.x, ty = threadIdx.y;
#pragma unroll
    for (int r = 0; r < 32; r += 8) {
        int n = n0 + ty + r;
        float dn = deg2dis(g_deg[layer][b * NN + n]);
        t[ty + r][tx] = __half2float(Fp[(size_t)b * NN * ND + (size_t)n * ND + d0 + tx]) * dn;
    }
    __syncthreads();
#pragma unroll
    for (int r = 0; r < 32; r += 8)
        Ft[(size_t)b * ND * NN + (size_t)(d0 + ty + r) * NN + n0 + tx] = __float2half(t[tx][ty + r]);
}

// ---------------- fp16 NT MMA GEMM, BK=64, 3-stage, 2 CTAs/SM ----------------
__device__ __forceinline__ void mma16816(float* d, const uint32_t* a, uint32_t b0, uint32_t b1) {
    asm volatile(
        "mma.sync.aligned.m16n8k16.row.col.f32.f16.f16.f32 "
        "{%0,%1,%2,%3},{%4,%5,%6,%7},{%8,%9},{%0,%1,%2,%3};\n"
        : "+f"(d[0]), "+f"(d[1]), "+f"(d[2]), "+f"(d[3])
        : "r"(a[0]), "r"(a[1]), "r"(a[2]), "r"(a[3]), "r"(b0), "r"(b1));
}

__device__ __forceinline__ void ldsm4(uint32_t& d0, uint32_t& d1, uint32_t& d2, uint32_t& d3,
                                      uint32_t addr) {
    asm volatile("ldmatrix.sync.aligned.m8n8.x4.shared.b16 {%0,%1,%2,%3}, [%4];\n"
                 : "=r"(d0), "=r"(d1), "=r"(d2), "=r"(d3) : "r"(addr));
}

__device__ __forceinline__ void cpa16(__half* dst, const __half* src) {
    uint32_t d = (uint32_t)__cvta_generic_to_shared(dst);
    asm volatile("cp.async.cg.shared.global [%0], [%1], 16;\n" :: "r"(d), "l"(src));
}

// EPI: 0 = fp16 store, 1 = gate, 2 = prop (dis scale, fp16 out only)
template <int EPI>
__global__ void __launch_bounds__(256, 2) k_mma(
    const __half* __restrict__ Ag, const __half* __restrict__ Bg,
    float* __restrict__ C, __half* __restrict__ O,
    int K, int lda, int ldb, int ldc,
    size_t bsA, size_t bsB, size_t bsC, size_t bsO,
    const float* __restrict__ pmask, int layer)
{
    extern __shared__ __align__(16) __half smem[];
    __shared__ float pmr[BM], pmc[BN];
    __shared__ float red[3][8];

    const int bz = blockIdx.z;
    Ag += bz * bsA; Bg += bz * bsB;
    if (EPI == 1) C += bz * bsC;
    O += bz * bsO;

    const int tid = threadIdx.x;
    const int m0 = blockIdx.y * BM;
    const int n0 = blockIdx.x * BN;

    if (EPI == 1) {
        if (tid < BM) pmr[tid] = pmask[bz * NN + m0 + tid];
        else          pmc[tid - BM] = pmask[bz * NN + n0 + (tid - BM)];
    }

    auto load_stage = [&](int s, int k0) {
        __half* dst = smem + s * SM_STAGE;
#pragma unroll
        for (int i = 0; i < 4; i++) {
            int q = i * 256 + tid, row = q >> 3, c = q & 7;
            cpa16(dst + SM_A + row * PP + c * 8, Ag + (size_t)(m0 + row) * lda + k0 + c * 8);
        }
#pragma unroll
        for (int i = 0; i < 4; i++) {
            int q = i * 256 + tid, row = q >> 3, c = q & 7;
            cpa16(dst + SM_B + row * PP + c * 8, Bg + (size_t)(n0 + row) * ldb + k0 + c * 8);
        }
        asm volatile("cp.async.commit_group;\n");
    };

    float acc[2][8][4];
#pragma unroll
    for (int mi = 0; mi < 2; mi++)
#pragma unroll
        for (int nj = 0; nj < 8; nj++)
#pragma unroll
            for (int q = 0; q < 4; q++) acc[mi][nj][q] = 0.f;

    const int lane = tid & 31;
    const int wid = tid >> 5;
    const int g = lane >> 2, t4 = lane & 3;
    const int wr = (wid & 3) * 32;
    const int wc = (wid >> 2) * 64;

    const uint32_t smem32 = (uint32_t)__cvta_generic_to_shared(smem);
    const int aRow = wr + (lane & 15);
    const int aKof = (lane >> 4) << 3;
    const int bRow = wc + (lane & 7) + ((lane >> 4) << 3);
    const int bKof = ((lane >> 3) & 1) << 3;

    const int KT = K / BK;
    load_stage(0, 0);
    load_stage(1, BK);

    for (int kt = 0; kt < KT; kt++) {
        int s = kt % 3;
        if (kt + 1 < KT) {
            asm volatile("cp.async.wait_group 1;\n");
        } else {
            asm volatile("cp.async.wait_group 0;\n");
        }
        __syncthreads();
        if (kt + 2 < KT) load_stage((kt + 2) % 3, (kt + 2) * BK);

        const uint32_t sA32 = smem32 + (s * SM_STAGE + SM_A) * 2;
        const uint32_t sB32 = smem32 + (s * SM_STAGE + SM_B) * 2;

#pragma unroll
        for (int kk = 0; kk < BK; kk += 16) {
            uint32_t af[2][4], bf[8][2];
#pragma unroll
            for (int mi = 0; mi < 2; mi++)
                ldsm4(af[mi][0], af[mi][1], af[mi][2], af[mi][3],
                      sA32 + ((aRow + 16 * mi) * PP + kk + aKof) * 2);
#pragma unroll
            for (int j = 0; j < 4; j++)
                ldsm4(bf[2 * j][0], bf[2 * j][1], bf[2 * j + 1][0], bf[2 * j + 1][1],
                      sB32 + ((bRow + 16 * j) * PP + kk + bKof) * 2);
#pragma unroll
            for (int nj = 0; nj < 8; nj++)
#pragma unroll
                for (int mi = 0; mi < 2; mi++)
                    mma16816(acc[mi][nj], af[mi], bf[nj][0], bf[nj][1]);
        }
    }

    // ---------------- epilogues ----------------
    if (EPI == 0) {
#pragma unroll
        for (int mi = 0; mi < 2; mi++) {
            const int R = m0 + wr + 16 * mi + g;
#pragma unroll
            for (int nj = 0; nj < 8; nj++) {
                const int Cc = n0 + wc + 8 * nj + 2 * t4;
                *(__half2*)(O + (size_t)R * ldc + Cc) =
                    __floats2half2_rn(acc[mi][nj][0], acc[mi][nj][1]);
                *(__half2*)(O + (size_t)(R + 8) * ldc + Cc) =
                    __floats2half2_rn(acc[mi][nj][2], acc[mi][nj][3]);
            }
        }
    } else if (EPI == 2) {
#pragma unroll
        for (int mi = 0; mi < 2; mi++) {
            const int R = m0 + wr + 16 * mi + g;
            const float s1 = deg2dis(g_deg[layer][bz * NN + R]);
            const float s2 = deg2dis(g_deg[layer][bz * NN + R + 8]);
#pragma unroll
            for (int nj = 0; nj < 8; nj++) {
                const int Cc = n0 + wc + 8 * nj + 2 * t4;
                *(__half2*)(O + (size_t)R * ldc + Cc) =
                    __floats2half2_rn(acc[mi][nj][0] * s1, acc[mi][nj][1] * s1);
                *(__half2*)(O + (size_t)(R + 8) * ldc + Cc) =
                    __floats2half2_rn(acc[mi][nj][2] * s2, acc[mi][nj][3] * s2);
            }
        }
    } else {  // gate
        float l0loc = 0.f, cloc = 0.f, gloc = 0.f;
#pragma unroll
        for (int mi = 0; mi < 2; mi++) {
            const int Rl = wr + 16 * mi + g;
            const int R = m0 + Rl;
            const float pr1 = pmr[Rl], pr2 = pmr[Rl + 8];
            float row1 = 0.f, row2 = 0.f;
#pragma unroll
            for (int nj = 0; nj < 8; nj++) {
                const int Ccl = wc + 8 * nj + 2 * t4;
                const int Cc = n0 + Ccl;
                const float pc0 = pmc[Ccl], pc1 = pmc[Ccl + 1];
                float v00 = (1.f / (1.f + expf(-acc[mi][nj][0] * SCALE_LOGIT))) * pr1 * pc0;
                float v01 = (1.f / (1.f + expf(-acc[mi][nj][1] * SCALE_LOGIT))) * pr1 * pc1;
                float v10 = (1.f / (1.f + expf(-acc[mi][nj][2] * SCALE_LOGIT))) * pr2 * pc0;
                float v11 = (1.f / (1.f + expf(-acc[mi][nj][3] * SCALE_LOGIT))) * pr2 * pc1;
                row1 += v00 + v01;
                row2 += v10 + v11;
                l0loc += v00 + v01 + v10 + v11;
                const bool c0ok = (Cc < NN - 1), c1ok = (Cc + 1 < NN - 1);
                float e1 = (c0ok ? v00 : 0.f) + (c1ok ? v01 : 0.f);
                float e2 = (c0ok ? v10 : 0.f) + (c1ok ? v11 : 0.f);
                if (R == NN - 1) cloc += e1; else gloc += e1;
                if (R + 8 == NN - 1) cloc += e2; else gloc += e2;
                *(float2*)(C + (size_t)R * ldc + Cc) = make_float2(v00, v01);
                *(float2*)(C + (size_t)(R + 8) * ldc + Cc) = make_float2(v10, v11);
                O[(size_t)Cc * NN + R]           = __float2half(v00);
                O[(size_t)(Cc + 1) * NN + R]     = __float2half(v01);
                O[(size_t)Cc * NN + R + 8]       = __float2half(v10);
                O[(size_t)(Cc + 1) * NN + R + 8] = __float2half(v11);
            }
            row1 += __shfl_xor_sync(0xffffffffu, row1, 1);
            row1 += __shfl_xor_sync(0xffffffffu, row1, 2);
            row2 += __shfl_xor_sync(0xffffffffu, row2, 1);
            row2 += __shfl_xor_sync(0xffffffffu, row2, 2);
            if (t4 == 0) {
                atomicAdd(&g_deg[layer][bz * NN + R], row1);
                atomicAdd(&g_deg[layer][bz * NN + R + 8], row2);
            }
        }
#pragma unroll
        for (int o = 16; o; o >>= 1) {
            l0loc += __shfl_xor_sync(0xffffffffu, l0loc, o);
            cloc  += __shfl_xor_sync(0xffffffffu, cloc, o);
            gloc  += __shfl_xor_sync(0xffffffffu, gloc, o);
        }
        if (lane == 0) { red[0][wid] = l0loc; red[1][wid] = cloc; red[2][wid] = gloc; }
        __syncthreads();
        if (tid == 0) {
            float a = 0.f, c = 0.f, gg = 0.f;
            for (int w = 0; w < 8; w++) { a += red[0][w]; c += red[1][w]; gg += red[2][w]; }
            atomicAdd(&g_l0, a);
            atomicAdd(&g_cacc[bz * NL + layer], c);
            atomicAdd(&g_gacc[bz * NL + layer], gg);
        }
    }
}

// ---------------- attention-pool epilogue (fp16 layer features) ----------------
__global__ void __launch_bounds__(256) k_final(
    const float* __restrict__ F0, const float* __restrict__ projw,
    const float* __restrict__ projb, float* __restrict__ out, float* __restrict__ retain)
{
    const int bn = blockIdx.x;
    const float* p0 = F0 + (size_t)bn * ND;
    const __half* p1 = g_F16[0] + (size_t)bn * ND;
    const __half* p2 = g_F16[1] + (size_t)bn * ND;
    const __half* p3 = g_F16[2] + (size_t)bn * ND;
    const __half* p4 = g_F16[3] + (size_t)bn * ND;
    float d0 = 0.f, d1 = 0.f, d2 = 0.f, d3 = 0.f, d4 = 0.f;
    for (int i = threadIdx.x; i < ND; i += 256) {
        float w = projw[i];
        d0 += p0[i] * w;
        d1 += __half2float(p1[i]) * w;
        d2 += __half2float(p2[i]) * w;
        d3 += __half2float(p3[i]) * w;
        d4 += __half2float(p4[i]) * w;
    }
#pragma unroll
    for (int o = 16; o; o >>= 1) {
        d0 += __shfl_xor_sync(0xffffffffu, d0, o);
        d1 += __shfl_xor_sync(0xffffffffu, d1, o);
        d2 += __shfl_xor_sync(0xffffffffu, d2, o);
        d3 += __shfl_xor_sync(0xffffffffu, d3, o);
        d4 += __shfl_xor_sync(0xffffffffu, d4, o);
    }
    __shared__ float sh[5][8], r[5];
    const int wid = threadIdx.x >> 5, lane = threadIdx.x & 31;
    if (lane == 0) { sh[0][wid] = d0; sh[1][wid] = d1; sh[2][wid] = d2; sh[3][wid] = d3; sh[4][wid] = d4; }
    __syncthreads();
    if (threadIdx.x < 5) {
        float t = 0.f;
        for (int w = 0; w < 8; w++) t += sh[threadIdx.x][w];
        float rr = 1.f / (1.f + expf(-(t + projb[0])));
        r[threadIdx.x] = rr;
        retain[(size_t)bn * (NL + 1) + threadIdx.x] = rr;
    }
    __syncthreads();
    const float r0 = r[0], r1 = r[1], r2 = r[2], r3 = r[3], r4 = r[4];
    for (int i = threadIdx.x; i < ND; i += 256)
        out[(size_t)bn * ND + i] = r0 * p0[i]
            + r1 * __half2float(p1[i]) + r2 * __half2float(p2[i])
            + r3 * __half2float(p3[i]) + r4 * __half2float(p4[i]);
}

__global__ void k_repack(float* __restrict__ adjs_out) {
    size_t i = (size_t)blockIdx.x * 256 + threadIdx.x;
    ((float4*)adjs_out)[i] = make_float4(g_adj[0][i], g_adj[1][i], g_adj[2][i], g_adj[3][i]);
}

__global__ void k_finalize(float* __restrict__ o_l0, float* __restrict__ o_c, float* __restrict__ o_g) {
    int t = threadIdx.x;
    if (t == 0) *o_l0 = g_l0 / ((g_fullsum + 1e-8f) * (float)NL);
    if (t < NB * NL) {
        int b = t / NL;
        float ps = g_psum[b];
        o_c[t] = g_cacc[t] / ps;
        o_g[t] = g_gacc[t] / (ps * ps);
    }
}

// ---------------- host orchestration ----------------
extern "C" void kernel_launch(void* const* d_in, const int* in_sizes, int n_in,
                              void* d_out, int out_size)
{
    (void)in_sizes; (void)n_in; (void)out_size;
    const float* pmask   = (const float*)d_in[0];
    const float* feature = (const float*)d_in[1];
    const float* Wq      = (const float*)d_in[2];
    const float* Wk      = (const float*)d_in[3];
    const float* projw   = (const float*)d_in[4];
    const float* projb   = (const float*)d_in[5];

    float* out    = (float*)d_out;
    float* retain = out + FS;
    float* adjs   = retain + (size_t)NB * NN * (NL + 1);
    float* o_l0   = adjs + AS * NL;
    float* o_c    = o_l0 + 1;
    float* o_g    = o_c + NB * NL;

    cudaFuncSetAttribute((const void*)&k_mma<0>, cudaFuncAttributeMaxDynamicSharedMemorySize, SMEM_BYTES);
    cudaFuncSetAttribute((const void*)&k_mma<1>, cudaFuncAttributeMaxDynamicSharedMemorySize, SMEM_BYTES);
    cudaFuncSetAttribute((const void*)&k_mma<2>, cudaFuncAttributeMaxDynamicSharedMemorySize, SMEM_BYTES);

    float *pAdj;
    __half *pF16, *pFp, *pWq16, *pWk16, *pMt, *pFt, *paT;
    cudaGetSymbolAddress((void**)&pAdj, g_adj);
    cudaGetSymbolAddress((void**)&pF16, g_F16);
    cudaGetSymbolAddress((void**)&pFp, g_Fp);
    cudaGetSymbolAddress((void**)&pWq16, g_Wq16);
    cudaGetSymbolAddress((void**)&pWk16, g_Wk16);
    cudaGetSymbolAddress((void**)&pMt, g_Mt);
    cudaGetSymbolAddress((void**)&pFt, g_Ft);
    cudaGetSymbolAddress((void**)&paT, g_aT);

    k_zero<<<256, 256>>>();
    k_init<<<NB, 256>>>(pmask);
    {
        int total = (int)(FS / 4) + 2 * (int)(NL * DD / 4);
        k_cvt3<<<(total + 255) / 256, 256>>>(
            (const float4*)feature, (const float4*)Wq, (const float4*)Wk,
            (__half2*)pFp, (__half2*)pWq16, (__half2*)pWk16);
    }

    // Mt[l] = Wk[l] * Wq[l]^T (fp16), batched over layers
    k_mma<0><<<dim3(ND / BN, ND / BM, NL), 256, SMEM_BYTES>>>(
        pWk16, pWq16, nullptr, pMt, ND, ND, ND, ND, DD, DD, 0, DD, nullptr, 0);

    for (int l = 0; l < NL; l++) {
        const __half* Fsrc = (l == 0) ? pFp : pF16 + (size_t)(l - 1) * FS;
        // G = F * Mt[l]^T (fp16 into g_Ft scratch)
        k_mma<0><<<dim3(ND / BN, (NB * NN) / BM, 1), 256, SMEM_BYTES>>>(
            Fsrc, pMt + (size_t)l * DD, nullptr, pFt,
            ND, ND, ND, ND, 0, 0, 0, 0, nullptr, 0);
        // adj = sigmoid(scale * G F^T) * mask (+deg/c/g/l0 + adjT fp16)
        k_mma<1><<<dim3(NN / BN, NN / BM, NB), 256, SMEM_BYTES>>>(
            pFt, Fsrc, pAdj + (size_t)l * AS, paT,
            ND, ND, ND, NN,
            (size_t)NN * ND, (size_t)NN * ND, (size_t)NN * NN, (size_t)NN * NN, pmask, l);
        // Ft = (F * dis[n])^T fp16 (overwrites G scratch)
        t_ft<<<dim3(ND / 32, NN / 32, NB), dim3(32, 8)>>>(Fsrc, pFt, l);
        // Fnext[m,d] = dis[m] * sum_n adjT[m,n]*Ft[d,n]  (fp16 only)
        k_mma<2><<<dim3(ND / BN, NN / BM, NB), 256, SMEM_BYTES>>>(
            paT, pFt, nullptr, pF16 + (size_t)l * FS,
            NN, NN, NN, ND,
            (size_t)NN * NN, (size_t)ND * NN, 0, (size_t)NN * ND, nullptr, l);
    }

    k_final<<<NB * NN, 256>>>(feature, projw, projb, out, retain);
    k_repack<<<(int)(AS / 256), 256>>>(adjs);
    k_finalize<<<1, 128>>>(o_l0, o_c, o_g);
}

// round 13
// speedup vs baseline: 1.1889x; 1.0303x over previous
#include <cuda_runtime.h>
#include <cuda_fp16.h>
#include <math.h>
#include <stdint.h>

#define NB 32
#define NN 512
#define ND 768
#define NL 4
#define FS ((size_t)NB * NN * ND)
#define AS ((size_t)NB * NN * NN)
#define DD ((size_t)ND * ND)
#define SCALE_LOGIT 0.03608439182435161f

// GEMM tiling: 128x128x64 tile, 256 threads (8 warps, 32x64 warp tile), 3-stage, 2 CTAs/SM
#define BM 128
#define BN 128
#define BK 64
#define PP 72
#define SM_A 0
#define SM_B (BM * PP)
#define SM_STAGE ((BM + BN) * PP)        // 18432 halves = 36864 B
#define SMEM_BYTES (3 * SM_STAGE * 2)    // 110592 B
#define TPITCH 136                       // adjT transpose buffer pitch (halves)

// ---------------- static device scratch ----------------
__device__ __align__(16) float g_adj[NL][NB * NN * NN];
__device__ __align__(16) __half g_F16[NL][NB * NN * ND];
__device__ __align__(16) __half g_Fp[FS];
__device__ __align__(16) __half g_Wq16[NL * DD], g_Wk16[NL * DD];
__device__ __align__(16) __half g_Mt[NL * DD];
__device__ __align__(16) __half g_Ft[NB * ND * NN];
__device__ __align__(16) __half g_aT[NB * NN * NN];
__device__ float g_deg[NL][NB * NN];
__device__ float g_psum[NB];
__device__ float g_fullsum, g_l0, g_cacc[NB * NL], g_gacc[NB * NL];

__device__ __forceinline__ float deg2dis(float d) {
    return (d > 0.f) ? rsqrtf(fmaxf(d, 1e-12f)) : 0.f;
}

// ---------------- fused prep: zero + psum init + fp32->fp16 converts ----------------
// blocks [0,256): zero scalars/deg; [256,288): per-batch psum; [288,...): cvt
__global__ void __launch_bounds__(256) k_prep(
    const float* __restrict__ pmask, const float4* __restrict__ f,
    const float4* __restrict__ wq, const float4* __restrict__ wk,
    __half2* __restrict__ hf, __half2* __restrict__ hwq, __half2* __restrict__ hwk)
{
    const int blk = blockIdx.x;
    if (blk < 256) {
        int i = blk * 256 + threadIdx.x;
        if (i < NL * NB * NN) ((float*)g_deg)[i] = 0.f;
        if (blk == 0) {
            if (threadIdx.x == 0) { g_l0 = 0.f; g_fullsum = 0.f; }
            if (threadIdx.x < NB * NL) { g_cacc[threadIdx.x] = 0.f; g_gacc[threadIdx.x] = 0.f; }
        }
        return;
    }
    if (blk < 288) {
        int b = blk - 256;
        float s = 0.f;
        for (int i = threadIdx.x; i < NN; i += 256) s += pmask[b * NN + i];
#pragma unroll
        for (int o = 16; o; o >>= 1) s += __shfl_xor_sync(0xffffffffu, s, o);
        __shared__ float sh[8];
        if ((threadIdx.x & 31) == 0) sh[threadIdx.x >> 5] = s;
        __syncthreads();
        if (threadIdx.x == 0) {
            float t = 0.f;
            for (int w = 0; w < 8; w++) t += sh[w];
            g_psum[b] = t;
            atomicAdd(&g_fullsum, t * t);
        }
        return;
    }
    const int NF = (int)(FS / 4), NW = (int)(NL * DD / 4);
    int i = (blk - 288) * 256 + threadIdx.x;
    const float4* src;
    __half2* dst;
    int j;
    if (i < NF) { src = f; dst = hf; j = i; }
    else if (i < NF + NW) { src = wq; dst = hwq; j = i - NF; }
    else if (i < NF + 2 * NW) { src = wk; dst = hwk; j = i - NF - NW; }
    else return;
    float4 v = src[j];
    dst[2 * j]     = __floats2half2_rn(v.x, v.y);
    dst[2 * j + 1] = __floats2half2_rn(v.z, v.w);
}

// Ft[b][d][n] = Fp[b][n][d] * dis(deg[layer][b][n])
__global__ void t_ft(const __half* __restrict__ Fp, __half* __restrict__ Ft, int layer) {
    int b = blockIdx.z, d0 = blockIdx.x * 32, n0 = blockIdx.y * 32;
    __shared__ float t[32][33];
    int tx = threadIdx.x, ty = threadIdx.y;
#pragma unroll
    for (int r = 0; r < 32; r += 8) {
        int n = n0 + ty + r;
        float dn = deg2dis(g_deg[layer][b * NN + n]);
        t[ty + r][tx] = __half2float(Fp[(size_t)b * NN * ND + (size_t)n * ND + d0 + tx]) * dn;
    }
    __syncthreads();
#pragma unroll
    for (int r = 0; r < 32; r += 8)
        Ft[(size_t)b * ND * NN + (size_t)(d0 + ty + r) * NN + n0 + tx] = __float2half(t[tx][ty + r]);
}

// ---------------- fp16 NT MMA GEMM, BK=64, 3-stage, 2 CTAs/SM ----------------
__device__ __forceinline__ void mma16816(float* d, const uint32_t* a, uint32_t b0, uint32_t b1) {
    asm volatile(
        "mma.sync.aligned.m16n8k16.row.col.f32.f16.f16.f32 "
        "{%0,%1,%2,%3},{%4,%5,%6,%7},{%8,%9},{%0,%1,%2,%3};\n"
        : "+f"(d[0]), "+f"(d[1]), "+f"(d[2]), "+f"(d[3])
        : "r"(a[0]), "r"(a[1]), "r"(a[2]), "r"(a[3]), "r"(b0), "r"(b1));
}

__device__ __forceinline__ void ldsm4(uint32_t& d0, uint32_t& d1, uint32_t& d2, uint32_t& d3,
                                      uint32_t addr) {
    asm volatile("ldmatrix.sync.aligned.m8n8.x4.shared.b16 {%0,%1,%2,%3}, [%4];\n"
                 : "=r"(d0), "=r"(d1), "=r"(d2), "=r"(d3) : "r"(addr));
}

__device__ __forceinline__ void cpa16(__half* dst, const __half* src) {
    uint32_t d = (uint32_t)__cvta_generic_to_shared(dst);
    asm volatile("cp.async.cg.shared.global [%0], [%1], 16;\n" :: "r"(d), "l"(src));
}

// EPI: 0 = fp16 store, 1 = gate (adj fp32 + adjT via smem transpose + reductions), 2 = prop
template <int EPI>
__global__ void __launch_bounds__(256, 2) k_mma(
    const __half* __restrict__ Ag, const __half* __restrict__ Bg,
    float* __restrict__ C, __half* __restrict__ O,
    int K, int lda, int ldb, int ldc,
    size_t bsA, size_t bsB, size_t bsC, size_t bsO,
    const float* __restrict__ pmask, int layer)
{
    extern __shared__ __align__(16) __half smem[];
    __shared__ float pmr[BM], pmc[BN];
    __shared__ float red[3][8];

    const int bz = blockIdx.z;
    Ag += bz * bsA; Bg += bz * bsB;
    if (EPI == 1) C += bz * bsC;
    O += bz * bsO;

    const int tid = threadIdx.x;
    const int m0 = blockIdx.y * BM;
    const int n0 = blockIdx.x * BN;

    if (EPI == 1) {
        if (tid < BM) pmr[tid] = pmask[bz * NN + m0 + tid];
        else          pmc[tid - BM] = pmask[bz * NN + n0 + (tid - BM)];
    }

    auto load_stage = [&](int s, int k0) {
        __half* dst = smem + s * SM_STAGE;
#pragma unroll
        for (int i = 0; i < 4; i++) {
            int q = i * 256 + tid, row = q >> 3, c = q & 7;
            cpa16(dst + SM_A + row * PP + c * 8, Ag + (size_t)(m0 + row) * lda + k0 + c * 8);
        }
#pragma unroll
        for (int i = 0; i < 4; i++) {
            int q = i * 256 + tid, row = q >> 3, c = q & 7;
            cpa16(dst + SM_B + row * PP + c * 8, Bg + (size_t)(n0 + row) * ldb + k0 + c * 8);
        }
        asm volatile("cp.async.commit_group;\n");
    };

    float acc[2][8][4];
#pragma unroll
    for (int mi = 0; mi < 2; mi++)
#pragma unroll
        for (int nj = 0; nj < 8; nj++)
#pragma unroll
            for (int q = 0; q < 4; q++) acc[mi][nj][q] = 0.f;

    const int lane = tid & 31;
    const int wid = tid >> 5;
    const int g = lane >> 2, t4 = lane & 3;
    const int wr = (wid & 3) * 32;
    const int wc = (wid >> 2) * 64;

    const uint32_t smem32 = (uint32_t)__cvta_generic_to_shared(smem);
    const int aRow = wr + (lane & 15);
    const int aKof = (lane >> 4) << 3;
    const int bRow = wc + (lane & 7) + ((lane >> 4) << 3);
    const int bKof = ((lane >> 3) & 1) << 3;

    const int KT = K / BK;
    load_stage(0, 0);
    load_stage(1, BK);

    for (int kt = 0; kt < KT; kt++) {
        int s = kt % 3;
        if (kt + 1 < KT) {
            asm volatile("cp.async.wait_group 1;\n");
        } else {
            asm volatile("cp.async.wait_group 0;\n");
        }
        __syncthreads();
        if (kt + 2 < KT) load_stage((kt + 2) % 3, (kt + 2) * BK);

        const uint32_t sA32 = smem32 + (s * SM_STAGE + SM_A) * 2;
        const uint32_t sB32 = smem32 + (s * SM_STAGE + SM_B) * 2;

#pragma unroll
        for (int kk = 0; kk < BK; kk += 16) {
            uint32_t af[2][4], bf[8][2];
#pragma unroll
            for (int mi = 0; mi < 2; mi++)
                ldsm4(af[mi][0], af[mi][1], af[mi][2], af[mi][3],
                      sA32 + ((aRow + 16 * mi) * PP + kk + aKof) * 2);
#pragma unroll
            for (int j = 0; j < 4; j++)
                ldsm4(bf[2 * j][0], bf[2 * j][1], bf[2 * j + 1][0], bf[2 * j + 1][1],
                      sB32 + ((bRow + 16 * j) * PP + kk + bKof) * 2);
#pragma unroll
            for (int nj = 0; nj < 8; nj++)
#pragma unroll
                for (int mi = 0; mi < 2; mi++)
                    mma16816(acc[mi][nj], af[mi], bf[nj][0], bf[nj][1]);
        }
    }

    // ---------------- epilogues ----------------
    if (EPI == 0) {
#pragma unroll
        for (int mi = 0; mi < 2; mi++) {
            const int R = m0 + wr + 16 * mi + g;
#pragma unroll
            for (int nj = 0; nj < 8; nj++) {
                const int Cc = n0 + wc + 8 * nj + 2 * t4;
                *(__half2*)(O + (size_t)R * ldc + Cc) =
                    __floats2half2_rn(acc[mi][nj][0], acc[mi][nj][1]);
                *(__half2*)(O + (size_t)(R + 8) * ldc + Cc) =
                    __floats2half2_rn(acc[mi][nj][2], acc[mi][nj][3]);
            }
        }
    } else if (EPI == 2) {
#pragma unroll
        for (int mi = 0; mi < 2; mi++) {
            const int R = m0 + wr + 16 * mi + g;
            const float s1 = deg2dis(g_deg[layer][bz * NN + R]);
            const float s2 = deg2dis(g_deg[layer][bz * NN + R + 8]);
#pragma unroll
            for (int nj = 0; nj < 8; nj++) {
                const int Cc = n0 + wc + 8 * nj + 2 * t4;
                *(__half2*)(O + (size_t)R * ldc + Cc) =
                    __floats2half2_rn(acc[mi][nj][0] * s1, acc[mi][nj][1] * s1);
                *(__half2*)(O + (size_t)(R + 8) * ldc + Cc) =
                    __floats2half2_rn(acc[mi][nj][2] * s2, acc[mi][nj][3] * s2);
            }
        }
    } else {  // gate
        __syncthreads();   // mainloop smem now dead; reuse as transpose buffer
        __half* tb = smem; // [BN][TPITCH] halves = 34816 B
        float l0loc = 0.f, cloc = 0.f, gloc = 0.f;
#pragma unroll
        for (int mi = 0; mi < 2; mi++) {
            const int Rl = wr + 16 * mi + g;
            const int R = m0 + Rl;
            const float pr1 = pmr[Rl], pr2 = pmr[Rl + 8];
            float row1 = 0.f, row2 = 0.f;
#pragma unroll
            for (int nj = 0; nj < 8; nj++) {
                const int Ccl = wc + 8 * nj + 2 * t4;
                const int Cc = n0 + Ccl;
                const float pc0 = pmc[Ccl], pc1 = pmc[Ccl + 1];
                float v00 = (1.f / (1.f + expf(-acc[mi][nj][0] * SCALE_LOGIT))) * pr1 * pc0;
                float v01 = (1.f / (1.f + expf(-acc[mi][nj][1] * SCALE_LOGIT))) * pr1 * pc1;
                float v10 = (1.f / (1.f + expf(-acc[mi][nj][2] * SCALE_LOGIT))) * pr2 * pc0;
                float v11 = (1.f / (1.f + expf(-acc[mi][nj][3] * SCALE_LOGIT))) * pr2 * pc1;
                row1 += v00 + v01;
                row2 += v10 + v11;
                l0loc += v00 + v01 + v10 + v11;
                const bool c0ok = (Cc < NN - 1), c1ok = (Cc + 1 < NN - 1);
                float e1 = (c0ok ? v00 : 0.f) + (c1ok ? v01 : 0.f);
                float e2 = (c0ok ? v10 : 0.f) + (c1ok ? v11 : 0.f);
                if (R == NN - 1) cloc += e1; else gloc += e1;
                if (R + 8 == NN - 1) cloc += e2; else gloc += e2;
                *(float2*)(C + (size_t)R * ldc + Cc) = make_float2(v00, v01);
                *(float2*)(C + (size_t)(R + 8) * ldc + Cc) = make_float2(v10, v11);
                tb[Ccl * TPITCH + Rl]           = __float2half(v00);
                tb[(Ccl + 1) * TPITCH + Rl]     = __float2half(v01);
                tb[Ccl * TPITCH + Rl + 8]       = __float2half(v10);
                tb[(Ccl + 1) * TPITCH + Rl + 8] = __float2half(v11);
            }
            row1 += __shfl_xor_sync(0xffffffffu, row1, 1);
            row1 += __shfl_xor_sync(0xffffffffu, row1, 2);
            row2 += __shfl_xor_sync(0xffffffffu, row2, 1);
            row2 += __shfl_xor_sync(0xffffffffu, row2, 2);
            if (t4 == 0) {
                atomicAdd(&g_deg[layer][bz * NN + R], row1);
                atomicAdd(&g_deg[layer][bz * NN + R + 8], row2);
            }
        }
        __syncthreads();
        // coalesced adjT write-out: row = adjT row (gate col), col pairs contiguous
        for (int e2 = tid; e2 < BN * (BM / 2); e2 += 256) {
            int row = e2 >> 6, col2 = e2 & 63;
            uint32_t v = *(const uint32_t*)&tb[row * TPITCH + 2 * col2];
            *(uint32_t*)(O + (size_t)(n0 + row) * NN + m0 + 2 * col2) = v;
        }
#pragma unroll
        for (int o = 16; o; o >>= 1) {
            l0loc += __shfl_xor_sync(0xffffffffu, l0loc, o);
            cloc  += __shfl_xor_sync(0xffffffffu, cloc, o);
            gloc  += __shfl_xor_sync(0xffffffffu, gloc, o);
        }
        if (lane == 0) { red[0][wid] = l0loc; red[1][wid] = cloc; red[2][wid] = gloc; }
        __syncthreads();
        if (tid == 0) {
            float a = 0.f, c = 0.f, gg = 0.f;
            for (int w = 0; w < 8; w++) { a += red[0][w]; c += red[1][w]; gg += red[2][w]; }
            atomicAdd(&g_l0, a);
            atomicAdd(&g_cacc[bz * NL + layer], c);
            atomicAdd(&g_gacc[bz * NL + layer], gg);
        }
    }
}

// ---------------- fused tail: attention-pool + repack + finalize ----------------
// blocks [0, NB*NN): k_final work; [NB*NN, NB*NN+AS/256): repack; last block: finalize
__global__ void __launch_bounds__(256) k_tail(
    const float* __restrict__ F0, const float* __restrict__ projw,
    const float* __restrict__ projb, float* __restrict__ out, float* __restrict__ retain,
    float* __restrict__ adjs_out,
    float* __restrict__ o_l0, float* __restrict__ o_c, float* __restrict__ o_g)
{
    const int blk = blockIdx.x;
    if (blk < NB * NN) {
        const int bn = blk;
        const float* p0 = F0 + (size_t)bn * ND;
        const __half* p1 = g_F16[0] + (size_t)bn * ND;
        const __half* p2 = g_F16[1] + (size_t)bn * ND;
        const __half* p3 = g_F16[2] + (size_t)bn * ND;
        const __half* p4 = g_F16[3] + (size_t)bn * ND;
        float d0 = 0.f, d1 = 0.f, d2 = 0.f, d3 = 0.f, d4 = 0.f;
        for (int i = threadIdx.x; i < ND; i += 256) {
            float w = projw[i];
            d0 += p0[i] * w;
            d1 += __half2float(p1[i]) * w;
            d2 += __half2float(p2[i]) * w;
            d3 += __half2float(p3[i]) * w;
            d4 += __half2float(p4[i]) * w;
        }
#pragma unroll
        for (int o = 16; o; o >>= 1) {
            d0 += __shfl_xor_sync(0xffffffffu, d0, o);
            d1 += __shfl_xor_sync(0xffffffffu, d1, o);
            d2 += __shfl_xor_sync(0xffffffffu, d2, o);
            d3 += __shfl_xor_sync(0xffffffffu, d3, o);
            d4 += __shfl_xor_sync(0xffffffffu, d4, o);
        }
        __shared__ float sh[5][8], r[5];
        const int wid = threadIdx.x >> 5, lane = threadIdx.x & 31;
        if (lane == 0) { sh[0][wid] = d0; sh[1][wid] = d1; sh[2][wid] = d2; sh[3][wid] = d3; sh[4][wid] = d4; }
        __syncthreads();
        if (threadIdx.x < 5) {
            float t = 0.f;
            for (int w = 0; w < 8; w++) t += sh[threadIdx.x][w];
            float rr = 1.f / (1.f + expf(-(t + projb[0])));
            r[threadIdx.x] = rr;
            retain[(size_t)bn * (NL + 1) + threadIdx.x] = rr;
        }
        __syncthreads();
        const float r0 = r[0], r1 = r[1], r2 = r[2], r3 = r[3], r4 = r[4];
        for (int i = threadIdx.x; i < ND; i += 256)
            out[(size_t)bn * ND + i] = r0 * p0[i]
                + r1 * __half2float(p1[i]) + r2 * __half2float(p2[i])
                + r3 * __half2float(p3[i]) + r4 * __half2float(p4[i]);
        return;
    }
    const int rblk = blk - NB * NN;
    if (rblk < (int)(AS / 256)) {
        size_t i = (size_t)rblk * 256 + threadIdx.x;
        ((float4*)adjs_out)[i] = make_float4(g_adj[0][i], g_adj[1][i], g_adj[2][i], g_adj[3][i]);
        return;
    }
    // finalize (single block)
    int t = threadIdx.x;
    if (t == 0) *o_l0 = g_l0 / ((g_fullsum + 1e-8f) * (float)NL);
    if (t < NB * NL) {
        int b = t / NL;
        float ps = g_psum[b];
        o_c[t] = g_cacc[t] / ps;
        o_g[t] = g_gacc[t] / (ps * ps);
    }
}

// ---------------- host orchestration ----------------
extern "C" void kernel_launch(void* const* d_in, const int* in_sizes, int n_in,
                              void* d_out, int out_size)
{
    (void)in_sizes; (void)n_in; (void)out_size;
    const float* pmask   = (const float*)d_in[0];
    const float* feature = (const float*)d_in[1];
    const float* Wq      = (const float*)d_in[2];
    const float* Wk      = (const float*)d_in[3];
    const float* projw   = (const float*)d_in[4];
    const float* projb   = (const float*)d_in[5];

    float* out    = (float*)d_out;
    float* retain = out + FS;
    float* adjs   = retain + (size_t)NB * NN * (NL + 1);
    float* o_l0   = adjs + AS * NL;
    float* o_c    = o_l0 + 1;
    float* o_g    = o_c + NB * NL;

    cudaFuncSetAttribute((const void*)&k_mma<0>, cudaFuncAttributeMaxDynamicSharedMemorySize, SMEM_BYTES);
    cudaFuncSetAttribute((const void*)&k_mma<1>, cudaFuncAttributeMaxDynamicSharedMemorySize, SMEM_BYTES);
    cudaFuncSetAttribute((const void*)&k_mma<2>, cudaFuncAttributeMaxDynamicSharedMemorySize, SMEM_BYTES);

    float *pAdj;
    __half *pF16, *pFp, *pWq16, *pWk16, *pMt, *pFt, *paT;
    cudaGetSymbolAddress((void**)&pAdj, g_adj);
    cudaGetSymbolAddress((void**)&pF16, g_F16);
    cudaGetSymbolAddress((void**)&pFp, g_Fp);
    cudaGetSymbolAddress((void**)&pWq16, g_Wq16);
    cudaGetSymbolAddress((void**)&pWk16, g_Wk16);
    cudaGetSymbolAddress((void**)&pMt, g_Mt);
    cudaGetSymbolAddress((void**)&pFt, g_Ft);
    cudaGetSymbolAddress((void**)&paT, g_aT);

    {
        int cvt_blocks = ((int)(FS / 4) + 2 * (int)(NL * DD / 4) + 255) / 256;
        k_prep<<<288 + cvt_blocks, 256>>>(
            pmask, (const float4*)feature, (const float4*)Wq, (const float4*)Wk,
            (__half2*)pFp, (__half2*)pWq16, (__half2*)pWk16);
    }

    // Mt[l] = Wk[l] * Wq[l]^T (fp16), batched over layers
    k_mma<0><<<dim3(ND / BN, ND / BM, NL), 256, SMEM_BYTES>>>(
        pWk16, pWq16, nullptr, pMt, ND, ND, ND, ND, DD, DD, 0, DD, nullptr, 0);

    for (int l = 0; l < NL; l++) {
        const __half* Fsrc = (l == 0) ? pFp : pF16 + (size_t)(l - 1) * FS;
        // G = F * Mt[l]^T (fp16 into g_Ft scratch)
        k_mma<0><<<dim3(ND / BN, (NB * NN) / BM, 1), 256, SMEM_BYTES>>>(
            Fsrc, pMt + (size_t)l * DD, nullptr, pFt,
            ND, ND, ND, ND, 0, 0, 0, 0, nullptr, 0);
        // adj = sigmoid(scale * G F^T) * mask (+deg/c/g/l0 + coalesced adjT)
        k_mma<1><<<dim3(NN / BN, NN / BM, NB), 256, SMEM_BYTES>>>(
            pFt, Fsrc, pAdj + (size_t)l * AS, paT,
            ND, ND, ND, NN,
            (size_t)NN * ND, (size_t)NN * ND, (size_t)NN * NN, (size_t)NN * NN, pmask, l);
        // Ft = (F * dis[n])^T fp16 (overwrites G scratch)
        t_ft<<<dim3(ND / 32, NN / 32, NB), dim3(32, 8)>>>(Fsrc, pFt, l);
        // Fnext[m,d] = dis[m] * sum_n adjT[m,n]*Ft[d,n]  (fp16)
        k_mma<2><<<dim3(ND / BN, NN / BM, NB), 256, SMEM_BYTES>>>(
            paT, pFt, nullptr, pF16 + (size_t)l * FS,
            NN, NN, NN, ND,
            (size_t)NN * NN, (size_t)ND * NN, 0, (size_t)NN * ND, nullptr, l);
    }

    k_tail<<<NB * NN + (int)(AS / 256) + 1, 256>>>(
        feature, projw, projb, out, retain, adjs, o_l0, o_c, o_g);
}

// round 14
// speedup vs baseline: 1.2132x; 1.0204x over previous
#include <cuda_runtime.h>
#include <cuda_fp16.h>
#include <math.h>
#include <stdint.h>

#define NB 32
#define NN 512
#define ND 768
#define NL 4
#define FS ((size_t)NB * NN * ND)
#define AS ((size_t)NB * NN * NN)
#define DD ((size_t)ND * ND)
#define SCALE_LOGIT 0.03608439182435161f

// GEMM tiling: 128x128x64 tile, 256 threads (8 warps, 32x64 warp tile), 3-stage, 2 CTAs/SM
#define BM 128
#define BN 128
#define BK 64
#define PP 72
#define SM_A 0
#define SM_B (BM * PP)
#define SM_STAGE ((BM + BN) * PP)        // 18432 halves = 36864 B
#define SMEM_BYTES (3 * SM_STAGE * 2)    // 110592 B
#define TPITCH 136                       // adjT transpose buffer pitch (halves)

// ---------------- static device scratch ----------------
__device__ __align__(16) __half g_adj16[NL][NB * NN * NN];  // adj fp16, [n][m]
__device__ __align__(16) __half g_F16[NL][NB * NN * ND];
__device__ __align__(16) __half g_Fp[FS];
__device__ __align__(16) __half g_Wq16[NL * DD], g_Wk16[NL * DD];
__device__ __align__(16) __half g_Mt[NL * DD];
__device__ __align__(16) __half g_Ft[NB * ND * NN];
__device__ __align__(16) __half g_aT[NB * NN * NN];
__device__ float g_deg[NL][NB * NN];
__device__ float g_psum[NB];
__device__ float g_fullsum, g_l0, g_cacc[NB * NL], g_gacc[NB * NL];

__device__ __forceinline__ float deg2dis(float d) {
    return (d > 0.f) ? rsqrtf(fmaxf(d, 1e-12f)) : 0.f;
}
__device__ __forceinline__ float fsig(float x) {
    return 1.f / (1.f + __expf(-x));
}

// ---------------- fused prep: zero + psum init + fp32->fp16 converts ----------------
__global__ void __launch_bounds__(256) k_prep(
    const float* __restrict__ pmask, const float4* __restrict__ f,
    const float4* __restrict__ wq, const float4* __restrict__ wk,
    __half2* __restrict__ hf, __half2* __restrict__ hwq, __half2* __restrict__ hwk)
{
    const int blk = blockIdx.x;
    if (blk < 256) {
        int i = blk * 256 + threadIdx.x;
        if (i < NL * NB * NN) ((float*)g_deg)[i] = 0.f;
        if (blk == 0) {
            if (threadIdx.x == 0) { g_l0 = 0.f; g_fullsum = 0.f; }
            if (threadIdx.x < NB * NL) { g_cacc[threadIdx.x] = 0.f; g_gacc[threadIdx.x] = 0.f; }
        }
        return;
    }
    if (blk < 288) {
        int b = blk - 256;
        float s = 0.f;
        for (int i = threadIdx.x; i < NN; i += 256) s += pmask[b * NN + i];
#pragma unroll
        for (int o = 16; o; o >>= 1) s += __shfl_xor_sync(0xffffffffu, s, o);
        __shared__ float sh[8];
        if ((threadIdx.x & 31) == 0) sh[threadIdx.x >> 5] = s;
        __syncthreads();
        if (threadIdx.x == 0) {
            float t = 0.f;
            for (int w = 0; w < 8; w++) t += sh[w];
            g_psum[b] = t;
            atomicAdd(&g_fullsum, t * t);
        }
        return;
    }
    const int NF = (int)(FS / 4), NW = (int)(NL * DD / 4);
    int i = (blk - 288) * 256 + threadIdx.x;
    const float4* src;
    __half2* dst;
    int j;
    if (i < NF) { src = f; dst = hf; j = i; }
    else if (i < NF + NW) { src = wq; dst = hwq; j = i - NF; }
    else if (i < NF + 2 * NW) { src = wk; dst = hwk; j = i - NF - NW; }
    else return;
    float4 v = src[j];
    dst[2 * j]     = __floats2half2_rn(v.x, v.y);
    dst[2 * j + 1] = __floats2half2_rn(v.z, v.w);
}

// Ft[b][d][n] = Fp[b][n][d] * dis(deg[layer][b][n])
__global__ void t_ft(const __half* __restrict__ Fp, __half* __restrict__ Ft, int layer) {
    int b = blockIdx.z, d0 = blockIdx.x * 32, n0 = blockIdx.y * 32;
    __shared__ float t[32][33];
    int tx = threadIdx.x, ty = threadIdx.y;
#pragma unroll
    for (int r = 0; r < 32; r += 8) {
        int n = n0 + ty + r;
        float dn = deg2dis(g_deg[layer][b * NN + n]);
        t[ty + r][tx] = __half2float(Fp[(size_t)b * NN * ND + (size_t)n * ND + d0 + tx]) * dn;
    }
    __syncthreads();
#pragma unroll
    for (int r = 0; r < 32; r += 8)
        Ft[(size_t)b * ND * NN + (size_t)(d0 + ty + r) * NN + n0 + tx] = __float2half(t[tx][ty + r]);
}

// ---------------- fp16 NT MMA GEMM, BK=64, 3-stage, 2 CTAs/SM ----------------
__device__ __forceinline__ void mma16816(float* d, const uint32_t* a, uint32_t b0, uint32_t b1) {
    asm volatile(
        "mma.sync.aligned.m16n8k16.row.col.f32.f16.f16.f32 "
        "{%0,%1,%2,%3},{%4,%5,%6,%7},{%8,%9},{%0,%1,%2,%3};\n"
        : "+f"(d[0]), "+f"(d[1]), "+f"(d[2]), "+f"(d[3])
        : "r"(a[0]), "r"(a[1]), "r"(a[2]), "r"(a[3]), "r"(b0), "r"(b1));
}

__device__ __forceinline__ void ldsm4(uint32_t& d0, uint32_t& d1, uint32_t& d2, uint32_t& d3,
                                      uint32_t addr) {
    asm volatile("ldmatrix.sync.aligned.m8n8.x4.shared.b16 {%0,%1,%2,%3}, [%4];\n"
                 : "=r"(d0), "=r"(d1), "=r"(d2), "=r"(d3) : "r"(addr));
}

__device__ __forceinline__ void cpa16(__half* dst, const __half* src) {
    uint32_t d = (uint32_t)__cvta_generic_to_shared(dst);
    asm volatile("cp.async.cg.shared.global [%0], [%1], 16;\n" :: "r"(d), "l"(src));
}

// EPI: 0 = fp16 store, 1 = gate (adj fp16 + adjT via smem transpose + reductions), 2 = prop
template <int EPI>
__global__ void __launch_bounds__(256, 2) k_mma(
    const __half* __restrict__ Ag, const __half* __restrict__ Bg,
    __half* __restrict__ C, __half* __restrict__ O,
    int K, int lda, int ldb, int ldc,
    size_t bsA, size_t bsB, size_t bsC, size_t bsO,
    const float* __restrict__ pmask, int layer)
{
    extern __shared__ __align__(16) __half smem[];
    __shared__ float pmr[BM], pmc[BN];
    __shared__ float red[3][8];

    const int bz = blockIdx.z;
    Ag += bz * bsA; Bg += bz * bsB;
    if (EPI == 1) C += bz * bsC;
    O += bz * bsO;

    const int tid = threadIdx.x;
    const int m0 = blockIdx.y * BM;
    const int n0 = blockIdx.x * BN;

    if (EPI == 1) {
        if (tid < BM) pmr[tid] = pmask[bz * NN + m0 + tid];
        else          pmc[tid - BM] = pmask[bz * NN + n0 + (tid - BM)];
    }

    auto load_stage = [&](int s, int k0) {
        __half* dst = smem + s * SM_STAGE;
#pragma unroll
        for (int i = 0; i < 4; i++) {
            int q = i * 256 + tid, row = q >> 3, c = q & 7;
            cpa16(dst + SM_A + row * PP + c * 8, Ag + (size_t)(m0 + row) * lda + k0 + c * 8);
        }
#pragma unroll
        for (int i = 0; i < 4; i++) {
            int q = i * 256 + tid, row = q >> 3, c = q & 7;
            cpa16(dst + SM_B + row * PP + c * 8, Bg + (size_t)(n0 + row) * ldb + k0 + c * 8);
        }
        asm volatile("cp.async.commit_group;\n");
    };

    float acc[2][8][4];
#pragma unroll
    for (int mi = 0; mi < 2; mi++)
#pragma unroll
        for (int nj = 0; nj < 8; nj++)
#pragma unroll
            for (int q = 0; q < 4; q++) acc[mi][nj][q] = 0.f;

    const int lane = tid & 31;
    const int wid = tid >> 5;
    const int g = lane >> 2, t4 = lane & 3;
    const int wr = (wid & 3) * 32;
    const int wc = (wid >> 2) * 64;

    const uint32_t smem32 = (uint32_t)__cvta_generic_to_shared(smem);
    const int aRow = wr + (lane & 15);
    const int aKof = (lane >> 4) << 3;
    const int bRow = wc + (lane & 7) + ((lane >> 4) << 3);
    const int bKof = ((lane >> 3) & 1) << 3;

    const int KT = K / BK;
    load_stage(0, 0);
    load_stage(1, BK);

    for (int kt = 0; kt < KT; kt++) {
        int s = kt % 3;
        if (kt + 1 < KT) {
            asm volatile("cp.async.wait_group 1;\n");
        } else {
            asm volatile("cp.async.wait_group 0;\n");
        }
        __syncthreads();
        if (kt + 2 < KT) load_stage((kt + 2) % 3, (kt + 2) * BK);

        const uint32_t sA32 = smem32 + (s * SM_STAGE + SM_A) * 2;
        const uint32_t sB32 = smem32 + (s * SM_STAGE + SM_B) * 2;

#pragma unroll
        for (int kk = 0; kk < BK; kk += 16) {
            uint32_t af[2][4], bf[8][2];
#pragma unroll
            for (int mi = 0; mi < 2; mi++)
                ldsm4(af[mi][0], af[mi][1], af[mi][2], af[mi][3],
                      sA32 + ((aRow + 16 * mi) * PP + kk + aKof) * 2);
#pragma unroll
            for (int j = 0; j < 4; j++)
                ldsm4(bf[2 * j][0], bf[2 * j][1], bf[2 * j + 1][0], bf[2 * j + 1][1],
                      sB32 + ((bRow + 16 * j) * PP + kk + bKof) * 2);
#pragma unroll
            for (int nj = 0; nj < 8; nj++)
#pragma unroll
                for (int mi = 0; mi < 2; mi++)
                    mma16816(acc[mi][nj], af[mi], bf[nj][0], bf[nj][1]);
        }
    }

    // ---------------- epilogues ----------------
    if (EPI == 0) {
#pragma unroll
        for (int mi = 0; mi < 2; mi++) {
            const int R = m0 + wr + 16 * mi + g;
#pragma unroll
            for (int nj = 0; nj < 8; nj++) {
                const int Cc = n0 + wc + 8 * nj + 2 * t4;
                *(__half2*)(O + (size_t)R * ldc + Cc) =
                    __floats2half2_rn(acc[mi][nj][0], acc[mi][nj][1]);
                *(__half2*)(O + (size_t)(R + 8) * ldc + Cc) =
                    __floats2half2_rn(acc[mi][nj][2], acc[mi][nj][3]);
            }
        }
    } else if (EPI == 2) {
#pragma unroll
        for (int mi = 0; mi < 2; mi++) {
            const int R = m0 + wr + 16 * mi + g;
            const float s1 = deg2dis(g_deg[layer][bz * NN + R]);
            const float s2 = deg2dis(g_deg[layer][bz * NN + R + 8]);
#pragma unroll
            for (int nj = 0; nj < 8; nj++) {
                const int Cc = n0 + wc + 8 * nj + 2 * t4;
                *(__half2*)(O + (size_t)R * ldc + Cc) =
                    __floats2half2_rn(acc[mi][nj][0] * s1, acc[mi][nj][1] * s1);
                *(__half2*)(O + (size_t)(R + 8) * ldc + Cc) =
                    __floats2half2_rn(acc[mi][nj][2] * s2, acc[mi][nj][3] * s2);
            }
        }
    } else {  // gate
        __syncthreads();   // mainloop smem dead; reuse as transpose buffer
        __half* tb = smem; // [BN][TPITCH]
        float l0loc = 0.f, cloc = 0.f, gloc = 0.f;
#pragma unroll
        for (int mi = 0; mi < 2; mi++) {
            const int Rl = wr + 16 * mi + g;
            const int R = m0 + Rl;
            const float pr1 = pmr[Rl], pr2 = pmr[Rl + 8];
            float row1 = 0.f, row2 = 0.f;
#pragma unroll
            for (int nj = 0; nj < 8; nj++) {
                const int Ccl = wc + 8 * nj + 2 * t4;
                const int Cc = n0 + Ccl;
                const float pc0 = pmc[Ccl], pc1 = pmc[Ccl + 1];
                float v00 = fsig(acc[mi][nj][0] * SCALE_LOGIT) * pr1 * pc0;
                float v01 = fsig(acc[mi][nj][1] * SCALE_LOGIT) * pr1 * pc1;
                float v10 = fsig(acc[mi][nj][2] * SCALE_LOGIT) * pr2 * pc0;
                float v11 = fsig(acc[mi][nj][3] * SCALE_LOGIT) * pr2 * pc1;
                row1 += v00 + v01;
                row2 += v10 + v11;
                l0loc += v00 + v01 + v10 + v11;
                const bool c0ok = (Cc < NN - 1), c1ok = (Cc + 1 < NN - 1);
                float e1 = (c0ok ? v00 : 0.f) + (c1ok ? v01 : 0.f);
                float e2 = (c0ok ? v10 : 0.f) + (c1ok ? v11 : 0.f);
                if (R == NN - 1) cloc += e1; else gloc += e1;
                if (R + 8 == NN - 1) cloc += e2; else gloc += e2;
                __half2 h1 = __floats2half2_rn(v00, v01);
                __half2 h2 = __floats2half2_rn(v10, v11);
                *(__half2*)(C + (size_t)R * ldc + Cc) = h1;
                *(__half2*)(C + (size_t)(R + 8) * ldc + Cc) = h2;
                tb[Ccl * TPITCH + Rl]           = __low2half(h1);
                tb[(Ccl + 1) * TPITCH + Rl]     = __high2half(h1);
                tb[Ccl * TPITCH + Rl + 8]       = __low2half(h2);
                tb[(Ccl + 1) * TPITCH + Rl + 8] = __high2half(h2);
            }
            row1 += __shfl_xor_sync(0xffffffffu, row1, 1);
            row1 += __shfl_xor_sync(0xffffffffu, row1, 2);
            row2 += __shfl_xor_sync(0xffffffffu, row2, 1);
            row2 += __shfl_xor_sync(0xffffffffu, row2, 2);
            if (t4 == 0) {
                atomicAdd(&g_deg[layer][bz * NN + R], row1);
                atomicAdd(&g_deg[layer][bz * NN + R + 8], row2);
            }
        }
        __syncthreads();
        for (int e2 = tid; e2 < BN * (BM / 2); e2 += 256) {
            int row = e2 >> 6, col2 = e2 & 63;
            uint32_t v = *(const uint32_t*)&tb[row * TPITCH + 2 * col2];
            *(uint32_t*)(O + (size_t)(n0 + row) * NN + m0 + 2 * col2) = v;
        }
#pragma unroll
        for (int o = 16; o; o >>= 1) {
            l0loc += __shfl_xor_sync(0xffffffffu, l0loc, o);
            cloc  += __shfl_xor_sync(0xffffffffu, cloc, o);
            gloc  += __shfl_xor_sync(0xffffffffu, gloc, o);
        }
        if (lane == 0) { red[0][wid] = l0loc; red[1][wid] = cloc; red[2][wid] = gloc; }
        __syncthreads();
        if (tid == 0) {
            float a = 0.f, c = 0.f, gg = 0.f;
            for (int w = 0; w < 8; w++) { a += red[0][w]; c += red[1][w]; gg += red[2][w]; }
            atomicAdd(&g_l0, a);
            atomicAdd(&g_cacc[bz * NL + layer], c);
            atomicAdd(&g_gacc[bz * NL + layer], gg);
        }
    }
}

// ---------------- fused tail: attention-pool + repack (fp16->fp32) + finalize ----------------
__global__ void __launch_bounds__(256) k_tail(
    const float* __restrict__ F0, const float* __restrict__ projw,
    const float* __restrict__ projb, float* __restrict__ out, float* __restrict__ retain,
    float* __restrict__ adjs_out,
    float* __restrict__ o_l0, float* __restrict__ o_c, float* __restrict__ o_g)
{
    const int blk = blockIdx.x;
    if (blk < NB * NN) {
        const int bn = blk;
        const float* p0 = F0 + (size_t)bn * ND;
        const __half* p1 = g_F16[0] + (size_t)bn * ND;
        const __half* p2 = g_F16[1] + (size_t)bn * ND;
        const __half* p3 = g_F16[2] + (size_t)bn * ND;
        const __half* p4 = g_F16[3] + (size_t)bn * ND;
        float d0 = 0.f, d1 = 0.f, d2 = 0.f, d3 = 0.f, d4 = 0.f;
        for (int i = threadIdx.x; i < ND; i += 256) {
            float w = projw[i];
            d0 += p0[i] * w;
            d1 += __half2float(p1[i]) * w;
            d2 += __half2float(p2[i]) * w;
            d3 += __half2float(p3[i]) * w;
            d4 += __half2float(p4[i]) * w;
        }
#pragma unroll
        for (int o = 16; o; o >>= 1) {
            d0 += __shfl_xor_sync(0xffffffffu, d0, o);
            d1 += __shfl_xor_sync(0xffffffffu, d1, o);
            d2 += __shfl_xor_sync(0xffffffffu, d2, o);
            d3 += __shfl_xor_sync(0xffffffffu, d3, o);
            d4 += __shfl_xor_sync(0xffffffffu, d4, o);
        }
        __shared__ float sh[5][8], r[5];
        const int wid = threadIdx.x >> 5, lane = threadIdx.x & 31;
        if (lane == 0) { sh[0][wid] = d0; sh[1][wid] = d1; sh[2][wid] = d2; sh[3][wid] = d3; sh[4][wid] = d4; }
        __syncthreads();
        if (threadIdx.x < 5) {
            float t = 0.f;
            for (int w = 0; w < 8; w++) t += sh[threadIdx.x][w];
            float rr = 1.f / (1.f + expf(-(t + projb[0])));
            r[threadIdx.x] = rr;
            retain[(size_t)bn * (NL + 1) + threadIdx.x] = rr;
        }
        __syncthreads();
        const float r0 = r[0], r1 = r[1], r2 = r[2], r3 = r[3], r4 = r[4];
        for (int i = threadIdx.x; i < ND; i += 256)
            out[(size_t)bn * ND + i] = r0 * p0[i]
                + r1 * __half2float(p1[i]) + r2 * __half2float(p2[i])
                + r3 * __half2float(p3[i]) + r4 * __half2float(p4[i]);
        return;
    }
    const int rblk = blk - NB * NN;
    if (rblk < (int)(AS / 256)) {
        size_t i = (size_t)rblk * 256 + threadIdx.x;
        ((float4*)adjs_out)[i] = make_float4(
            __half2float(g_adj16[0][i]), __half2float(g_adj16[1][i]),
            __half2float(g_adj16[2][i]), __half2float(g_adj16[3][i]));
        return;
    }
    int t = threadIdx.x;
    if (t == 0) *o_l0 = g_l0 / ((g_fullsum + 1e-8f) * (float)NL);
    if (t < NB * NL) {
        int b = t / NL;
        float ps = g_psum[b];
        o_c[t] = g_cacc[t] / ps;
        o_g[t] = g_gacc[t] / (ps * ps);
    }
}

// ---------------- host orchestration ----------------
extern "C" void kernel_launch(void* const* d_in, const int* in_sizes, int n_in,
                              void* d_out, int out_size)
{
    (void)in_sizes; (void)n_in; (void)out_size;
    const float* pmask   = (const float*)d_in[0];
    const float* feature = (const float*)d_in[1];
    const float* Wq      = (const float*)d_in[2];
    const float* Wk      = (const float*)d_in[3];
    const float* projw   = (const float*)d_in[4];
    const float* projb   = (const float*)d_in[5];

    float* out    = (float*)d_out;
    float* retain = out + FS;
    float* adjs   = retain + (size_t)NB * NN * (NL + 1);
    float* o_l0   = adjs + AS * NL;
    float* o_c    = o_l0 + 1;
    float* o_g    = o_c + NB * NL;

    cudaFuncSetAttribute((const void*)&k_mma<0>, cudaFuncAttributeMaxDynamicSharedMemorySize, SMEM_BYTES);
    cudaFuncSetAttribute((const void*)&k_mma<1>, cudaFuncAttributeMaxDynamicSharedMemorySize, SMEM_BYTES);
    cudaFuncSetAttribute((const void*)&k_mma<2>, cudaFuncAttributeMaxDynamicSharedMemorySize, SMEM_BYTES);

    __half *pAdj16, *pF16, *pFp, *pWq16, *pWk16, *pMt, *pFt, *paT;
    cudaGetSymbolAddress((void**)&pAdj16, g_adj16);
    cudaGetSymbolAddress((void**)&pF16, g_F16);
    cudaGetSymbolAddress((void**)&pFp, g_Fp);
    cudaGetSymbolAddress((void**)&pWq16, g_Wq16);
    cudaGetSymbolAddress((void**)&pWk16, g_Wk16);
    cudaGetSymbolAddress((void**)&pMt, g_Mt);
    cudaGetSymbolAddress((void**)&pFt, g_Ft);
    cudaGetSymbolAddress((void**)&paT, g_aT);

    {
        int cvt_blocks = ((int)(FS / 4) + 2 * (int)(NL * DD / 4) + 255) / 256;
        k_prep<<<288 + cvt_blocks, 256>>>(
            pmask, (const float4*)feature, (const float4*)Wq, (const float4*)Wk,
            (__half2*)pFp, (__half2*)pWq16, (__half2*)pWk16);
    }

    // Mt[l] = Wk[l] * Wq[l]^T (fp16), batched over layers
    k_mma<0><<<dim3(ND / BN, ND / BM, NL), 256, SMEM_BYTES>>>(
        pWk16, pWq16, nullptr, pMt, ND, ND, ND, ND, DD, DD, 0, DD, nullptr, 0);

    for (int l = 0; l < NL; l++) {
        const __half* Fsrc = (l == 0) ? pFp : pF16 + (size_t)(l - 1) * FS;
        // G = F * Mt[l]^T (fp16 into g_Ft scratch)
        k_mma<0><<<dim3(ND / BN, (NB * NN) / BM, 1), 256, SMEM_BYTES>>>(
            Fsrc, pMt + (size_t)l * DD, nullptr, pFt,
            ND, ND, ND, ND, 0, 0, 0, 0, nullptr, 0);
        // adj = sigmoid(scale * G F^T) * mask (+deg/c/g/l0 + coalesced adjT, fp16 adj)
        k_mma<1><<<dim3(NN / BN, NN / BM, NB), 256, SMEM_BYTES>>>(
            pFt, Fsrc, pAdj16 + (size_t)l * AS, paT,
            ND, ND, ND, NN,
            (size_t)NN * ND, (size_t)NN * ND, (size_t)NN * NN, (size_t)NN * NN, pmask, l);
        // Ft = (F * dis[n])^T fp16 (overwrites G scratch)
        t_ft<<<dim3(ND / 32, NN / 32, NB), dim3(32, 8)>>>(Fsrc, pFt, l);
        // Fnext[m,d] = dis[m] * sum_n adjT[m,n]*Ft[d,n]  (fp16)
        k_mma<2><<<dim3(ND / BN, NN / BM, NB), 256, SMEM_BYTES>>>(
            paT, pFt, nullptr, pF16 + (size_t)l * FS,
            NN, NN, NN, ND,
            (size_t)NN * NN, (size_t)ND * NN, 0, (size_t)NN * ND, nullptr, l);
    }

    k_tail<<<NB * NN + (int)(AS / 256) + 1, 256>>>(
        feature, projw, projb, out, retain, adjs, o_l0, o_c, o_g);
}

// round 15
// speedup vs baseline: 1.2169x; 1.0030x over previous
#include <cuda_runtime.h>
#include <cuda_fp16.h>
#include <math.h>
#include <stdint.h>

#define NB 32
#define NN 512
#define ND 768
#define NL 4
#define FS ((size_t)NB * NN * ND)
#define AS ((size_t)NB * NN * NN)
#define DD ((size_t)ND * ND)
#define SCALE_LOGIT 0.03608439182435161f

#define BM 128
#define BN 128
#define BK 64
#define PP 72
#define SM_A 0
#define SM_B (BM * PP)
#define SM_STAGE ((BM + BN) * PP)        // 18432 halves = 36864 B
#define SMEM_BYTES (3 * SM_STAGE * 2)    // 110592 B
#define TPITCH 136

// ---------------- static device scratch ----------------
__device__ __align__(16) __half g_aT16[NL][NB * NN * NN];   // adj^T fp16 per layer
__device__ __align__(16) __half g_F16[NL][NB * NN * ND];
__device__ __align__(16) __half g_Fp[FS];
__device__ __align__(16) __half g_Wq16[NL * DD], g_Wk16[NL * DD];
__device__ __align__(16) __half g_Mt[NL * DD];
__device__ __align__(16) __half g_Ft[NB * ND * NN];
__device__ float g_deg[NL][NB * NN];
__device__ float g_psum[NB];
__device__ float g_fullsum, g_l0, g_cacc[NB * NL], g_gacc[NB * NL];

__device__ __forceinline__ float deg2dis(float d) {
    return (d > 0.f) ? rsqrtf(fmaxf(d, 1e-12f)) : 0.f;
}
__device__ __forceinline__ float fsig(float x) {
    return 1.f / (1.f + __expf(-x));
}

// ---------------- fused prep ----------------
__global__ void __launch_bounds__(256) k_prep(
    const float* __restrict__ pmask, const float4* __restrict__ f,
    const float4* __restrict__ wq, const float4* __restrict__ wk,
    __half2* __restrict__ hf, __half2* __restrict__ hwq, __half2* __restrict__ hwk)
{
    const int blk = blockIdx.x;
    if (blk < 256) {
        int i = blk * 256 + threadIdx.x;
        if (i < NL * NB * NN) ((float*)g_deg)[i] = 0.f;
        if (blk == 0) {
            if (threadIdx.x == 0) { g_l0 = 0.f; g_fullsum = 0.f; }
            if (threadIdx.x < NB * NL) { g_cacc[threadIdx.x] = 0.f; g_gacc[threadIdx.x] = 0.f; }
        }
        return;
    }
    if (blk < 288) {
        int b = blk - 256;
        float s = 0.f;
        for (int i = threadIdx.x; i < NN; i += 256) s += pmask[b * NN + i];
#pragma unroll
        for (int o = 16; o; o >>= 1) s += __shfl_xor_sync(0xffffffffu, s, o);
        __shared__ float sh[8];
        if ((threadIdx.x & 31) == 0) sh[threadIdx.x >> 5] = s;
        __syncthreads();
        if (threadIdx.x == 0) {
            float t = 0.f;
            for (int w = 0; w < 8; w++) t += sh[w];
            g_psum[b] = t;
            atomicAdd(&g_fullsum, t * t);
        }
        return;
    }
    const int NF = (int)(FS / 4), NW = (int)(NL * DD / 4);
    int i = (blk - 288) * 256 + threadIdx.x;
    const float4* src;
    __half2* dst;
    int j;
    if (i < NF) { src = f; dst = hf; j = i; }
    else if (i < NF + NW) { src = wq; dst = hwq; j = i - NF; }
    else if (i < NF + 2 * NW) { src = wk; dst = hwk; j = i - NF - NW; }
    else return;
    float4 v = src[j];
    dst[2 * j]     = __floats2half2_rn(v.x, v.y);
    dst[2 * j + 1] = __floats2half2_rn(v.z, v.w);
}

// Ft[b][d][n] = Fp[b][n][d] * dis(deg[layer][b][n])
__global__ void t_ft(const __half* __restrict__ Fp, __half* __restrict__ Ft, int layer) {
    int b = blockIdx.z, d0 = blockIdx.x * 32, n0 = blockIdx.y * 32;
    __shared__ float t[32][33];
    int tx = threadIdx.x, ty = threadIdx.y;
#pragma unroll
    for (int r = 0; r < 32; r += 8) {
        int n = n0 + ty + r;
        float dn = deg2dis(g_deg[layer][b * NN + n]);
        t[ty + r][tx] = __half2float(Fp[(size_t)b * NN * ND + (size_t)n * ND + d0 + tx]) * dn;
    }
    __syncthreads();
#pragma unroll
    for (int r = 0; r < 32; r += 8)
        Ft[(size_t)b * ND * NN + (size_t)(d0 + ty + r) * NN + n0 + tx] = __float2half(t[tx][ty + r]);
}

// ---------------- fp16 NT MMA GEMM, BK=64, 3-stage, 2 CTAs/SM ----------------
__device__ __forceinline__ void mma16816(float* d, const uint32_t* a, uint32_t b0, uint32_t b1) {
    asm volatile(
        "mma.sync.aligned.m16n8k16.row.col.f32.f16.f16.f32 "
        "{%0,%1,%2,%3},{%4,%5,%6,%7},{%8,%9},{%0,%1,%2,%3};\n"
        : "+f"(d[0]), "+f"(d[1]), "+f"(d[2]), "+f"(d[3])
        : "r"(a[0]), "r"(a[1]), "r"(a[2]), "r"(a[3]), "r"(b0), "r"(b1));
}

__device__ __forceinline__ void ldsm4(uint32_t& d0, uint32_t& d1, uint32_t& d2, uint32_t& d3,
                                      uint32_t addr) {
    asm volatile("ldmatrix.sync.aligned.m8n8.x4.shared.b16 {%0,%1,%2,%3}, [%4];\n"
                 : "=r"(d0), "=r"(d1), "=r"(d2), "=r"(d3) : "r"(addr));
}

__device__ __forceinline__ void cpa16(__half* dst, const __half* src) {
    uint32_t d = (uint32_t)__cvta_generic_to_shared(dst);
    asm volatile("cp.async.cg.shared.global [%0], [%1], 16;\n" :: "r"(d), "l"(src));
}

// EPI: 0 = fp16 store, 1 = gate (adjT only + reductions), 2 = prop
template <int EPI>
__global__ void __launch_bounds__(256, 2) k_mma(
    const __half* __restrict__ Ag, const __half* __restrict__ Bg,
    __half* __restrict__ O,
    int K, int lda, int ldb, int ldc,
    size_t bsA, size_t bsB, size_t bsO,
    const float* __restrict__ pmask, int layer)
{
    extern __shared__ __align__(16) __half smem[];
    __shared__ float pmr[BM], pmc[BN];
    __shared__ float red[3][8];

    const int bz = blockIdx.z;
    Ag += bz * bsA; Bg += bz * bsB;
    O += bz * bsO;

    const int tid = threadIdx.x;
    const int m0 = blockIdx.y * BM;
    const int n0 = blockIdx.x * BN;

    if (EPI == 1) {
        if (tid < BM) pmr[tid] = pmask[bz * NN + m0 + tid];
        else          pmc[tid - BM] = pmask[bz * NN + n0 + (tid - BM)];
    }

    auto load_stage = [&](int s, int k0) {
        __half* dst = smem + s * SM_STAGE;
#pragma unroll
        for (int i = 0; i < 4; i++) {
            int q = i * 256 + tid, row = q >> 3, c = q & 7;
            cpa16(dst + SM_A + row * PP + c * 8, Ag + (size_t)(m0 + row) * lda + k0 + c * 8);
        }
#pragma unroll
        for (int i = 0; i < 4; i++) {
            int q = i * 256 + tid, row = q >> 3, c = q & 7;
            cpa16(dst + SM_B + row * PP + c * 8, Bg + (size_t)(n0 + row) * ldb + k0 + c * 8);
        }
        asm volatile("cp.async.commit_group;\n");
    };

    float acc[2][8][4];
#pragma unroll
    for (int mi = 0; mi < 2; mi++)
#pragma unroll
        for (int nj = 0; nj < 8; nj++)
#pragma unroll
            for (int q = 0; q < 4; q++) acc[mi][nj][q] = 0.f;

    const int lane = tid & 31;
    const int wid = tid >> 5;
    const int g = lane >> 2, t4 = lane & 3;
    const int wr = (wid & 3) * 32;
    const int wc = (wid >> 2) * 64;

    const uint32_t smem32 = (uint32_t)__cvta_generic_to_shared(smem);
    const int aRow = wr + (lane & 15);
    const int aKof = (lane >> 4) << 3;
    const int bRow = wc + (lane & 7) + ((lane >> 4) << 3);
    const int bKof = ((lane >> 3) & 1) << 3;

    const int KT = K / BK;
    load_stage(0, 0);
    load_stage(1, BK);

    for (int kt = 0; kt < KT; kt++) {
        int s = kt % 3;
        if (kt + 1 < KT) {
            asm volatile("cp.async.wait_group 1;\n");
        } else {
            asm volatile("cp.async.wait_group 0;\n");
        }
        __syncthreads();
        if (kt + 2 < KT) load_stage((kt + 2) % 3, (kt + 2) * BK);

        const uint32_t sA32 = smem32 + (s * SM_STAGE + SM_A) * 2;
        const uint32_t sB32 = smem32 + (s * SM_STAGE + SM_B) * 2;

#pragma unroll
        for (int kk = 0; kk < BK; kk += 16) {
            uint32_t af[2][4], bf[8][2];
#pragma unroll
            for (int mi = 0; mi < 2; mi++)
                ldsm4(af[mi][0], af[mi][1], af[mi][2], af[mi][3],
                      sA32 + ((aRow + 16 * mi) * PP + kk + aKof) * 2);
#pragma unroll
            for (int j = 0; j < 4; j++)
                ldsm4(bf[2 * j][0], bf[2 * j][1], bf[2 * j + 1][0], bf[2 * j + 1][1],
                      sB32 + ((bRow + 16 * j) * PP + kk + bKof) * 2);
#pragma unroll
            for (int nj = 0; nj < 8; nj++)
#pragma unroll
                for (int mi = 0; mi < 2; mi++)
                    mma16816(acc[mi][nj], af[mi], bf[nj][0], bf[nj][1]);
        }
    }

    // ---------------- epilogues ----------------
    if (EPI == 0) {
#pragma unroll
        for (int mi = 0; mi < 2; mi++) {
            const int R = m0 + wr + 16 * mi + g;
#pragma unroll
            for (int nj = 0; nj < 8; nj++) {
                const int Cc = n0 + wc + 8 * nj + 2 * t4;
                *(__half2*)(O + (size_t)R * ldc + Cc) =
                    __floats2half2_rn(acc[mi][nj][0], acc[mi][nj][1]);
                *(__half2*)(O + (size_t)(R + 8) * ldc + Cc) =
                    __floats2half2_rn(acc[mi][nj][2], acc[mi][nj][3]);
            }
        }
    } else if (EPI == 2) {
#pragma unroll
        for (int mi = 0; mi < 2; mi++) {
            const int R = m0 + wr + 16 * mi + g;
            const float s1 = deg2dis(g_deg[layer][bz * NN + R]);
            const float s2 = deg2dis(g_deg[layer][bz * NN + R + 8]);
#pragma unroll
            for (int nj = 0; nj < 8; nj++) {
                const int Cc = n0 + wc + 8 * nj + 2 * t4;
                *(__half2*)(O + (size_t)R * ldc + Cc) =
                    __floats2half2_rn(acc[mi][nj][0] * s1, acc[mi][nj][1] * s1);
                *(__half2*)(O + (size_t)(R + 8) * ldc + Cc) =
                    __floats2half2_rn(acc[mi][nj][2] * s2, acc[mi][nj][3] * s2);
            }
        }
    } else {  // gate: adjT only
        __syncthreads();
        __half* tb = smem;
        const bool edge = (m0 + BM >= NN) || (n0 + BN >= NN);
        float l0loc = 0.f, cloc = 0.f, gloc = 0.f;
#pragma unroll
        for (int mi = 0; mi < 2; mi++) {
            const int Rl = wr + 16 * mi + g;
            const int R = m0 + Rl;
            const float pr1 = pmr[Rl], pr2 = pmr[Rl + 8];
            float row1 = 0.f, row2 = 0.f;
#pragma unroll
            for (int nj = 0; nj < 8; nj++) {
                const int Ccl = wc + 8 * nj + 2 * t4;
                const int Cc = n0 + Ccl;
                const float pc0 = pmc[Ccl], pc1 = pmc[Ccl + 1];
                float v00 = fsig(acc[mi][nj][0] * SCALE_LOGIT) * pr1 * pc0;
                float v01 = fsig(acc[mi][nj][1] * SCALE_LOGIT) * pr1 * pc1;
                float v10 = fsig(acc[mi][nj][2] * SCALE_LOGIT) * pr2 * pc0;
                float v11 = fsig(acc[mi][nj][3] * SCALE_LOGIT) * pr2 * pc1;
                row1 += v00 + v01;
                row2 += v10 + v11;
                l0loc += v00 + v01 + v10 + v11;
                if (edge) {
                    const bool c0ok = (Cc < NN - 1), c1ok = (Cc + 1 < NN - 1);
                    float e1 = (c0ok ? v00 : 0.f) + (c1ok ? v01 : 0.f);
                    float e2 = (c0ok ? v10 : 0.f) + (c1ok ? v11 : 0.f);
                    if (R == NN - 1) cloc += e1; else gloc += e1;
                    if (R + 8 == NN - 1) cloc += e2; else gloc += e2;
                }
                __half2 h1 = __floats2half2_rn(v00, v01);
                __half2 h2 = __floats2half2_rn(v10, v11);
                tb[Ccl * TPITCH + Rl]           = __low2half(h1);
                tb[(Ccl + 1) * TPITCH + Rl]     = __high2half(h1);
                tb[Ccl * TPITCH + Rl + 8]       = __low2half(h2);
                tb[(Ccl + 1) * TPITCH + Rl + 8] = __high2half(h2);
            }
            row1 += __shfl_xor_sync(0xffffffffu, row1, 1);
            row1 += __shfl_xor_sync(0xffffffffu, row1, 2);
            row2 += __shfl_xor_sync(0xffffffffu, row2, 1);
            row2 += __shfl_xor_sync(0xffffffffu, row2, 2);
            if (t4 == 0) {
                atomicAdd(&g_deg[layer][bz * NN + R], row1);
                atomicAdd(&g_deg[layer][bz * NN + R + 8], row2);
            }
        }
        if (!edge) gloc = l0loc;
        __syncthreads();
        for (int e2 = tid; e2 < BN * (BM / 2); e2 += 256) {
            int row = e2 >> 6, col2 = e2 & 63;
            uint32_t v = *(const uint32_t*)&tb[row * TPITCH + 2 * col2];
            *(uint32_t*)(O + (size_t)(n0 + row) * NN + m0 + 2 * col2) = v;
        }
#pragma unroll
        for (int o = 16; o; o >>= 1) {
            l0loc += __shfl_xor_sync(0xffffffffu, l0loc, o);
            cloc  += __shfl_xor_sync(0xffffffffu, cloc, o);
            gloc  += __shfl_xor_sync(0xffffffffu, gloc, o);
        }
        if (lane == 0) { red[0][wid] = l0loc; red[1][wid] = cloc; red[2][wid] = gloc; }
        __syncthreads();
        if (tid == 0) {
            float a = 0.f, c = 0.f, gg = 0.f;
            for (int w = 0; w < 8; w++) { a += red[0][w]; c += red[1][w]; gg += red[2][w]; }
            atomicAdd(&g_l0, a);
            atomicAdd(&g_cacc[bz * NL + layer], c);
            atomicAdd(&g_gacc[bz * NL + layer], gg);
        }
    }
}

// ---------------- fused tail: attention-pool + transposed repack + finalize ----------------
// blocks [0, NB*NN): pool; [NB*NN, NB*NN + NB*256): repack (32x32 tiles); last: finalize
__global__ void __launch_bounds__(256) k_tail(
    const float* __restrict__ F0, const float* __restrict__ projw,
    const float* __restrict__ projb, float* __restrict__ out, float* __restrict__ retain,
    float* __restrict__ adjs_out,
    float* __restrict__ o_l0, float* __restrict__ o_c, float* __restrict__ o_g)
{
    const int blk = blockIdx.x;
    if (blk < NB * NN) {
        const int bn = blk;
        const float* p0 = F0 + (size_t)bn * ND;
        const __half* p1 = g_F16[0] + (size_t)bn * ND;
        const __half* p2 = g_F16[1] + (size_t)bn * ND;
        const __half* p3 = g_F16[2] + (size_t)bn * ND;
        const __half* p4 = g_F16[3] + (size_t)bn * ND;
        float d0 = 0.f, d1 = 0.f, d2 = 0.f, d3 = 0.f, d4 = 0.f;
        for (int i = threadIdx.x; i < ND; i += 256) {
            float w = projw[i];
            d0 += p0[i] * w;
            d1 += __half2float(p1[i]) * w;
            d2 += __half2float(p2[i]) * w;
            d3 += __half2float(p3[i]) * w;
            d4 += __half2float(p4[i]) * w;
        }
#pragma unroll
        for (int o = 16; o; o >>= 1) {
            d0 += __shfl_xor_sync(0xffffffffu, d0, o);
            d1 += __shfl_xor_sync(0xffffffffu, d1, o);
            d2 += __shfl_xor_sync(0xffffffffu, d2, o);
            d3 += __shfl_xor_sync(0xffffffffu, d3, o);
            d4 += __shfl_xor_sync(0xffffffffu, d4, o);
        }
        __shared__ float sh[5][8], r[5];
        const int wid = threadIdx.x >> 5, lane = threadIdx.x & 31;
        if (lane == 0) { sh[0][wid] = d0; sh[1][wid] = d1; sh[2][wid] = d2; sh[3][wid] = d3; sh[4][wid] = d4; }
        __syncthreads();
        if (threadIdx.x < 5) {
            float t = 0.f;
            for (int w = 0; w < 8; w++) t += sh[threadIdx.x][w];
            float rr = 1.f / (1.f + expf(-(t + projb[0])));
            r[threadIdx.x] = rr;
            retain[(size_t)bn * (NL + 1) + threadIdx.x] = rr;
        }
        __syncthreads();
        const float r0 = r[0], r1 = r[1], r2 = r[2], r3 = r[3], r4 = r[4];
        for (int i = threadIdx.x; i < ND; i += 256)
            out[(size_t)bn * ND + i] = r0 * p0[i]
                + r1 * __half2float(p1[i]) + r2 * __half2float(p2[i])
                + r3 * __half2float(p3[i]) + r4 * __half2float(p4[i]);
        return;
    }
    const int rblk = blk - NB * NN;
    if (rblk < NB * 256) {
        // transposed repack: adjs[b][n][m][l] = adjT[l][b][m][n]
        const int b = rblk >> 8;
        const int mt = (rblk & 255) >> 4;    // m tile
        const int nt = rblk & 15;            // n tile
        __shared__ __half s[NL][32][33];
        const int tx = threadIdx.x & 31;     // n within tile (read) / m (write)
        const int ty8 = threadIdx.x >> 5;    // 8 rows per pass
#pragma unroll
        for (int l = 0; l < NL; l++)
#pragma unroll
            for (int r = 0; r < 32; r += 8) {
                int m = mt * 32 + ty8 + r;
                s[l][ty8 + r][tx] = g_aT16[l][(size_t)b * NN * NN + (size_t)m * NN + nt * 32 + tx];
            }
        __syncthreads();
#pragma unroll
        for (int r = 0; r < 32; r += 8) {
            int n = nt * 32 + ty8 + r;
            int m = mt * 32 + tx;
            float4 v = make_float4(
                __half2float(s[0][tx][ty8 + r]), __half2float(s[1][tx][ty8 + r]),
                __half2float(s[2][tx][ty8 + r]), __half2float(s[3][tx][ty8 + r]));
            ((float4*)adjs_out)[(size_t)(b * NN + n) * NN + m] = v;
        }
        return;
    }
    int t = threadIdx.x;
    if (t == 0) *o_l0 = g_l0 / ((g_fullsum + 1e-8f) * (float)NL);
    if (t < NB * NL) {
        int b = t / NL;
        float ps = g_psum[b];
        o_c[t] = g_cacc[t] / ps;
        o_g[t] = g_gacc[t] / (ps * ps);
    }
}

// ---------------- host orchestration ----------------
extern "C" void kernel_launch(void* const* d_in, const int* in_sizes, int n_in,
                              void* d_out, int out_size)
{
    (void)in_sizes; (void)n_in; (void)out_size;
    const float* pmask   = (const float*)d_in[0];
    const float* feature = (const float*)d_in[1];
    const float* Wq      = (const float*)d_in[2];
    const float* Wk      = (const float*)d_in[3];
    const float* projw   = (const float*)d_in[4];
    const float* projb   = (const float*)d_in[5];

    float* out    = (float*)d_out;
    float* retain = out + FS;
    float* adjs   = retain + (size_t)NB * NN * (NL + 1);
    float* o_l0   = adjs + AS * NL;
    float* o_c    = o_l0 + 1;
    float* o_g    = o_c + NB * NL;

    cudaFuncSetAttribute((const void*)&k_mma<0>, cudaFuncAttributeMaxDynamicSharedMemorySize, SMEM_BYTES);
    cudaFuncSetAttribute((const void*)&k_mma<1>, cudaFuncAttributeMaxDynamicSharedMemorySize, SMEM_BYTES);
    cudaFuncSetAttribute((const void*)&k_mma<2>, cudaFuncAttributeMaxDynamicSharedMemorySize, SMEM_BYTES);

    __half *paT16, *pF16, *pFp, *pWq16, *pWk16, *pMt, *pFt;
    cudaGetSymbolAddress((void**)&paT16, g_aT16);
    cudaGetSymbolAddress((void**)&pF16, g_F16);
    cudaGetSymbolAddress((void**)&pFp, g_Fp);
    cudaGetSymbolAddress((void**)&pWq16, g_Wq16);
    cudaGetSymbolAddress((void**)&pWk16, g_Wk16);
    cudaGetSymbolAddress((void**)&pMt, g_Mt);
    cudaGetSymbolAddress((void**)&pFt, g_Ft);

    {
        int cvt_blocks = ((int)(FS / 4) + 2 * (int)(NL * DD / 4) + 255) / 256;
        k_prep<<<288 + cvt_blocks, 256>>>(
            pmask, (const float4*)feature, (const float4*)Wq, (const float4*)Wk,
            (__half2*)pFp, (__half2*)pWq16, (__half2*)pWk16);
    }

    // Mt[l] = Wk[l] * Wq[l]^T (fp16), batched over layers
    k_mma<0><<<dim3(ND / BN, ND / BM, NL), 256, SMEM_BYTES>>>(
        pWk16, pWq16, pMt, ND, ND, ND, ND, DD, DD, DD, nullptr, 0);

    for (int l = 0; l < NL; l++) {
        const __half* Fsrc = (l == 0) ? pFp : pF16 + (size_t)(l - 1) * FS;
        // G = F * Mt[l]^T (fp16 into g_Ft scratch)
        k_mma<0><<<dim3(ND / BN, (NB * NN) / BM, 1), 256, SMEM_BYTES>>>(
            Fsrc, pMt + (size_t)l * DD, pFt,
            ND, ND, ND, ND, 0, 0, 0, nullptr, 0);
        // gate: adjT[l] fp16 only (+deg/c/g/l0)
        k_mma<1><<<dim3(NN / BN, NN / BM, NB), 256, SMEM_BYTES>>>(
            pFt, Fsrc, paT16 + (size_t)l * AS,
            ND, ND, ND, NN,
            (size_t)NN * ND, (size_t)NN * ND, (size_t)NN * NN, pmask, l);
        // Ft = (F * dis[n])^T fp16 (overwrites G scratch)
        t_ft<<<dim3(ND / 32, NN / 32, NB), dim3(32, 8)>>>(Fsrc, pFt, l);
        // Fnext[m,d] = dis[m] * sum_n adjT[m,n]*Ft[d,n]  (fp16)
        k_mma<2><<<dim3(ND / BN, NN / BM, NB), 256, SMEM_BYTES>>>(
            paT16 + (size_t)l * AS, pFt, pF16 + (size_t)l * FS,
            NN, NN, NN, ND,
            (size_t)NN * NN, (size_t)ND * NN, (size_t)NN * ND, nullptr, l);
    }

    k_tail<<<NB * NN + NB * 256 + 1, 256>>>(
        feature, projw, projb, out, retain, adjs, o_l0, o_c, o_g);
}

// round 16
// speedup vs baseline: 1.2488x; 1.0262x over previous
#include <cuda_runtime.h>
#include <cuda_fp16.h>
#include <math.h>
#include <stdint.h>

#define NB 32
#define NN 512
#define ND 768
#define NL 4
#define FS ((size_t)NB * NN * ND)
#define AS ((size_t)NB * NN * NN)
#define DD ((size_t)ND * ND)
#define SCALE_LOGIT 0.03608439182435161f

#define BM 128
#define BN 128
#define BK 64
#define PP 72
#define SM_A 0
#define SM_B (BM * PP)
#define SM_STAGE ((BM + BN) * PP)        // 18432 halves = 36864 B
#define SMEM_BYTES (3 * SM_STAGE * 2)    // 110592 B
#define TPITCH 136

// ---------------- static device scratch ----------------
__device__ __align__(16) __half g_aT16[NL][NB * NN * NN];   // adj^T fp16 per layer
__device__ __align__(16) __half g_F16[NL][NB * NN * ND];
__device__ __align__(16) __half g_Fp[FS];
__device__ __align__(16) __half g_Wq16[NL * DD], g_Wk16[NL * DD];
__device__ __align__(16) __half g_Mt[NL * DD];
__device__ __align__(16) __half g_Ft[NB * ND * NN];
__device__ float g_deg[NL][NB * NN];
__device__ float g_psum[NB];
__device__ float g_fullsum, g_l0, g_cacc[NB * NL], g_gacc[NB * NL];

__device__ __forceinline__ float deg2dis(float d) {
    return (d > 0.f) ? rsqrtf(fmaxf(d, 1e-12f)) : 0.f;
}
__device__ __forceinline__ float fsig(float x) {
    return 1.f / (1.f + __expf(-x));
}

// ---------------- fused prep ----------------
__global__ void __launch_bounds__(256) k_prep(
    const float* __restrict__ pmask, const float4* __restrict__ f,
    const float4* __restrict__ wq, const float4* __restrict__ wk,
    __half2* __restrict__ hf, __half2* __restrict__ hwq, __half2* __restrict__ hwk)
{
    const int blk = blockIdx.x;
    if (blk < 256) {
        int i = blk * 256 + threadIdx.x;
        if (i < NL * NB * NN) ((float*)g_deg)[i] = 0.f;
        if (blk == 0) {
            if (threadIdx.x == 0) { g_l0 = 0.f; g_fullsum = 0.f; }
            if (threadIdx.x < NB * NL) { g_cacc[threadIdx.x] = 0.f; g_gacc[threadIdx.x] = 0.f; }
        }
        return;
    }
    if (blk < 288) {
        int b = blk - 256;
        float s = 0.f;
        for (int i = threadIdx.x; i < NN; i += 256) s += pmask[b * NN + i];
#pragma unroll
        for (int o = 16; o; o >>= 1) s += __shfl_xor_sync(0xffffffffu, s, o);
        __shared__ float sh[8];
        if ((threadIdx.x & 31) == 0) sh[threadIdx.x >> 5] = s;
        __syncthreads();
        if (threadIdx.x == 0) {
            float t = 0.f;
            for (int w = 0; w < 8; w++) t += sh[w];
            g_psum[b] = t;
            atomicAdd(&g_fullsum, t * t);
        }
        return;
    }
    const int NF = (int)(FS / 4), NW = (int)(NL * DD / 4);
    int i = (blk - 288) * 256 + threadIdx.x;
    const float4* src;
    __half2* dst;
    int j;
    if (i < NF) { src = f; dst = hf; j = i; }
    else if (i < NF + NW) { src = wq; dst = hwq; j = i - NF; }
    else if (i < NF + 2 * NW) { src = wk; dst = hwk; j = i - NF - NW; }
    else return;
    float4 v = src[j];
    dst[2 * j]     = __floats2half2_rn(v.x, v.y);
    dst[2 * j + 1] = __floats2half2_rn(v.z, v.w);
}

// Ft[b][d][n] = Fp[b][n][d] * dis(deg[layer][b][n])
__global__ void t_ft(const __half* __restrict__ Fp, __half* __restrict__ Ft, int layer) {
    int b = blockIdx.z, d0 = blockIdx.x * 32, n0 = blockIdx.y * 32;
    __shared__ float t[32][33];
    int tx = threadIdx.x, ty = threadIdx.y;
#pragma unroll
    for (int r = 0; r < 32; r += 8) {
        int n = n0 + ty + r;
        float dn = deg2dis(g_deg[layer][b * NN + n]);
        t[ty + r][tx] = __half2float(Fp[(size_t)b * NN * ND + (size_t)n * ND + d0 + tx]) * dn;
    }
    __syncthreads();
#pragma unroll
    for (int r = 0; r < 32; r += 8)
        Ft[(size_t)b * ND * NN + (size_t)(d0 + ty + r) * NN + n0 + tx] = __float2half(t[tx][ty + r]);
}

// ---------------- fp16 NT MMA GEMM, BK=64, 3-stage, 2 CTAs/SM ----------------
__device__ __forceinline__ void mma16816(float* d, const uint32_t* a, uint32_t b0, uint32_t b1) {
    asm volatile(
        "mma.sync.aligned.m16n8k16.row.col.f32.f16.f16.f32 "
        "{%0,%1,%2,%3},{%4,%5,%6,%7},{%8,%9},{%0,%1,%2,%3};\n"
        : "+f"(d[0]), "+f"(d[1]), "+f"(d[2]), "+f"(d[3])
        : "r"(a[0]), "r"(a[1]), "r"(a[2]), "r"(a[3]), "r"(b0), "r"(b1));
}

__device__ __forceinline__ void ldsm4(uint32_t& d0, uint32_t& d1, uint32_t& d2, uint32_t& d3,
                                      uint32_t addr) {
    asm volatile("ldmatrix.sync.aligned.m8n8.x4.shared.b16 {%0,%1,%2,%3}, [%4];\n"
                 : "=r"(d0), "=r"(d1), "=r"(d2), "=r"(d3) : "r"(addr));
}

__device__ __forceinline__ void cpa16(__half* dst, const __half* src) {
    uint32_t d = (uint32_t)__cvta_generic_to_shared(dst);
    asm volatile("cp.async.cg.shared.global [%0], [%1], 16;\n" :: "r"(d), "l"(src));
}

// EPI: 0 = fp16 store, 1 = gate (adjT only + reductions), 2 = prop (k-block skip on masked n)
template <int EPI>
__global__ void __launch_bounds__(256, 2) k_mma(
    const __half* __restrict__ Ag, const __half* __restrict__ Bg,
    __half* __restrict__ O,
    int K, int lda, int ldb, int ldc,
    size_t bsA, size_t bsB, size_t bsO,
    const float* __restrict__ pmask, int layer)
{
    extern __shared__ __align__(16) __half smem[];
    __shared__ float pmr[BM], pmc[BN];
    __shared__ float red[3][8];

    const int bz = blockIdx.z;
    Ag += bz * bsA; Bg += bz * bsB;
    O += bz * bsO;

    const int tid = threadIdx.x;
    const int m0 = blockIdx.y * BM;
    const int n0 = blockIdx.x * BN;

    if (EPI == 1) {
        if (tid < BM) pmr[tid] = pmask[bz * NN + m0 + tid];
        else          pmc[tid - BM] = pmask[bz * NN + n0 + (tid - BM)];
    }

    auto load_stage = [&](int s, int k0) {
        __half* dst = smem + s * SM_STAGE;
#pragma unroll
        for (int i = 0; i < 4; i++) {
            int q = i * 256 + tid, row = q >> 3, c = q & 7;
            cpa16(dst + SM_A + row * PP + c * 8, Ag + (size_t)(m0 + row) * lda + k0 + c * 8);
        }
#pragma unroll
        for (int i = 0; i < 4; i++) {
            int q = i * 256 + tid, row = q >> 3, c = q & 7;
            cpa16(dst + SM_B + row * PP + c * 8, Bg + (size_t)(n0 + row) * ldb + k0 + c * 8);
        }
        asm volatile("cp.async.commit_group;\n");
    };

    float acc[2][8][4];
#pragma unroll
    for (int mi = 0; mi < 2; mi++)
#pragma unroll
        for (int nj = 0; nj < 8; nj++)
#pragma unroll
            for (int q = 0; q < 4; q++) acc[mi][nj][q] = 0.f;

    const int lane = tid & 31;
    const int wid = tid >> 5;
    const int g = lane >> 2, t4 = lane & 3;
    const int wr = (wid & 3) * 32;
    const int wc = (wid >> 2) * 64;

    const uint32_t smem32 = (uint32_t)__cvta_generic_to_shared(smem);
    const int aRow = wr + (lane & 15);
    const int aKof = (lane >> 4) << 3;
    const int bRow = wc + (lane & 7) + ((lane >> 4) << 3);
    const int bKof = ((lane >> 3) & 1) << 3;

    // k-block schedule: prop (EPI==2) skips blocks covering only masked-out n.
    // valid n = [0,len) U {511}; len = psum-1. blocks 0..C-1 plus block 7 (CLS).
    int KT = K / BK;
    int Cv = KT;  // contiguous valid block count
    if (EPI == 2) {
        int len = (int)(g_psum[bz] + 0.5f) - 1;
        Cv = (len + BK - 1) / BK;
        KT = (Cv >= K / BK) ? (K / BK) : (Cv + 1);
    }
    const int LASTB = K / BK - 1;
#define KBLK(i) ((EPI == 2 && (i) >= Cv) ? LASTB : (i))

    load_stage(0, KBLK(0) * BK);
    load_stage(1, KBLK(1) * BK);

    for (int kt = 0; kt < KT; kt++) {
        int s = kt % 3;
        if (kt + 1 < KT) {
            asm volatile("cp.async.wait_group 1;\n");
        } else {
            asm volatile("cp.async.wait_group 0;\n");
        }
        __syncthreads();
        if (kt + 2 < KT) load_stage((kt + 2) % 3, KBLK(kt + 2) * BK);

        const uint32_t sA32 = smem32 + (s * SM_STAGE + SM_A) * 2;
        const uint32_t sB32 = smem32 + (s * SM_STAGE + SM_B) * 2;

#pragma unroll
        for (int kk = 0; kk < BK; kk += 16) {
            uint32_t af[2][4], bf[8][2];
#pragma unroll
            for (int mi = 0; mi < 2; mi++)
                ldsm4(af[mi][0], af[mi][1], af[mi][2], af[mi][3],
                      sA32 + ((aRow + 16 * mi) * PP + kk + aKof) * 2);
#pragma unroll
            for (int j = 0; j < 4; j++)
                ldsm4(bf[2 * j][0], bf[2 * j][1], bf[2 * j + 1][0], bf[2 * j + 1][1],
                      sB32 + ((bRow + 16 * j) * PP + kk + bKof) * 2);
#pragma unroll
            for (int nj = 0; nj < 8; nj++)
#pragma unroll
                for (int mi = 0; mi < 2; mi++)
                    mma16816(acc[mi][nj], af[mi], bf[nj][0], bf[nj][1]);
        }
    }
#undef KBLK

    // ---------------- epilogues ----------------
    if (EPI == 0) {
#pragma unroll
        for (int mi = 0; mi < 2; mi++) {
            const int R = m0 + wr + 16 * mi + g;
#pragma unroll
            for (int nj = 0; nj < 8; nj++) {
                const int Cc = n0 + wc + 8 * nj + 2 * t4;
                *(__half2*)(O + (size_t)R * ldc + Cc) =
                    __floats2half2_rn(acc[mi][nj][0], acc[mi][nj][1]);
                *(__half2*)(O + (size_t)(R + 8) * ldc + Cc) =
                    __floats2half2_rn(acc[mi][nj][2], acc[mi][nj][3]);
            }
        }
    } else if (EPI == 2) {
#pragma unroll
        for (int mi = 0; mi < 2; mi++) {
            const int R = m0 + wr + 16 * mi + g;
            const float s1 = deg2dis(g_deg[layer][bz * NN + R]);
            const float s2 = deg2dis(g_deg[layer][bz * NN + R + 8]);
#pragma unroll
            for (int nj = 0; nj < 8; nj++) {
                const int Cc = n0 + wc + 8 * nj + 2 * t4;
                *(__half2*)(O + (size_t)R * ldc + Cc) =
                    __floats2half2_rn(acc[mi][nj][0] * s1, acc[mi][nj][1] * s1);
                *(__half2*)(O + (size_t)(R + 8) * ldc + Cc) =
                    __floats2half2_rn(acc[mi][nj][2] * s2, acc[mi][nj][3] * s2);
            }
        }
    } else {  // gate: adjT only
        __syncthreads();
        __half* tb = smem;
        const bool edge = (m0 + BM >= NN) || (n0 + BN >= NN);
        float l0loc = 0.f, cloc = 0.f, gloc = 0.f;
#pragma unroll
        for (int mi = 0; mi < 2; mi++) {
            const int Rl = wr + 16 * mi + g;
            const int R = m0 + Rl;
            const float pr1 = pmr[Rl], pr2 = pmr[Rl + 8];
            float row1 = 0.f, row2 = 0.f;
#pragma unroll
            for (int nj = 0; nj < 8; nj++) {
                const int Ccl = wc + 8 * nj + 2 * t4;
                const int Cc = n0 + Ccl;
                const float pc0 = pmc[Ccl], pc1 = pmc[Ccl + 1];
                float v00 = fsig(acc[mi][nj][0] * SCALE_LOGIT) * pr1 * pc0;
                float v01 = fsig(acc[mi][nj][1] * SCALE_LOGIT) * pr1 * pc1;
                float v10 = fsig(acc[mi][nj][2] * SCALE_LOGIT) * pr2 * pc0;
                float v11 = fsig(acc[mi][nj][3] * SCALE_LOGIT) * pr2 * pc1;
                row1 += v00 + v01;
                row2 += v10 + v11;
                l0loc += v00 + v01 + v10 + v11;
                if (edge) {
                    const bool c0ok = (Cc < NN - 1), c1ok = (Cc + 1 < NN - 1);
                    float e1 = (c0ok ? v00 : 0.f) + (c1ok ? v01 : 0.f);
                    float e2 = (c0ok ? v10 : 0.f) + (c1ok ? v11 : 0.f);
                    if (R == NN - 1) cloc += e1; else gloc += e1;
                    if (R + 8 == NN - 1) cloc += e2; else gloc += e2;
                }
                __half2 h1 = __floats2half2_rn(v00, v01);
                __half2 h2 = __floats2half2_rn(v10, v11);
                tb[Ccl * TPITCH + Rl]           = __low2half(h1);
                tb[(Ccl + 1) * TPITCH + Rl]     = __high2half(h1);
                tb[Ccl * TPITCH + Rl + 8]       = __low2half(h2);
                tb[(Ccl + 1) * TPITCH + Rl + 8] = __high2half(h2);
            }
            row1 += __shfl_xor_sync(0xffffffffu, row1, 1);
            row1 += __shfl_xor_sync(0xffffffffu, row1, 2);
            row2 += __shfl_xor_sync(0xffffffffu, row2, 1);
            row2 += __shfl_xor_sync(0xffffffffu, row2, 2);
            if (t4 == 0) {
                atomicAdd(&g_deg[layer][bz * NN + R], row1);
                atomicAdd(&g_deg[layer][bz * NN + R + 8], row2);
            }
        }
        if (!edge) gloc = l0loc;
        __syncthreads();
        for (int e2 = tid; e2 < BN * (BM / 2); e2 += 256) {
            int row = e2 >> 6, col2 = e2 & 63;
            uint32_t v = *(const uint32_t*)&tb[row * TPITCH + 2 * col2];
            *(uint32_t*)(O + (size_t)(n0 + row) * NN + m0 + 2 * col2) = v;
        }
#pragma unroll
        for (int o = 16; o; o >>= 1) {
            l0loc += __shfl_xor_sync(0xffffffffu, l0loc, o);
            cloc  += __shfl_xor_sync(0xffffffffu, cloc, o);
            gloc  += __shfl_xor_sync(0xffffffffu, gloc, o);
        }
        if (lane == 0) { red[0][wid] = l0loc; red[1][wid] = cloc; red[2][wid] = gloc; }
        __syncthreads();
        if (tid == 0) {
            float a = 0.f, c = 0.f, gg = 0.f;
            for (int w = 0; w < 8; w++) { a += red[0][w]; c += red[1][w]; gg += red[2][w]; }
            atomicAdd(&g_l0, a);
            atomicAdd(&g_cacc[bz * NL + layer], c);
            atomicAdd(&g_gacc[bz * NL + layer], gg);
        }
    }
}

// ---------------- fused tail: attention-pool + transposed repack + finalize ----------------
__global__ void __launch_bounds__(256) k_tail(
    const float* __restrict__ F0, const float* __restrict__ projw,
    const float* __restrict__ projb, float* __restrict__ out, float* __restrict__ retain,
    float* __restrict__ adjs_out,
    float* __restrict__ o_l0, float* __restrict__ o_c, float* __restrict__ o_g)
{
    const int blk = blockIdx.x;
    if (blk < NB * NN) {
        const int bn = blk;
        const float* p0 = F0 + (size_t)bn * ND;
        const __half* p1 = g_F16[0] + (size_t)bn * ND;
        const __half* p2 = g_F16[1] + (size_t)bn * ND;
        const __half* p3 = g_F16[2] + (size_t)bn * ND;
        const __half* p4 = g_F16[3] + (size_t)bn * ND;
        float d0 = 0.f, d1 = 0.f, d2 = 0.f, d3 = 0.f, d4 = 0.f;
        for (int i = threadIdx.x; i < ND; i += 256) {
            float w = projw[i];
            d0 += p0[i] * w;
            d1 += __half2float(p1[i]) * w;
            d2 += __half2float(p2[i]) * w;
            d3 += __half2float(p3[i]) * w;
            d4 += __half2float(p4[i]) * w;
        }
#pragma unroll
        for (int o = 16; o; o >>= 1) {
            d0 += __shfl_xor_sync(0xffffffffu, d0, o);
            d1 += __shfl_xor_sync(0xffffffffu, d1, o);
            d2 += __shfl_xor_sync(0xffffffffu, d2, o);
            d3 += __shfl_xor_sync(0xffffffffu, d3, o);
            d4 += __shfl_xor_sync(0xffffffffu, d4, o);
        }
        __shared__ float sh[5][8], r[5];
        const int wid = threadIdx.x >> 5, lane = threadIdx.x & 31;
        if (lane == 0) { sh[0][wid] = d0; sh[1][wid] = d1; sh[2][wid] = d2; sh[3][wid] = d3; sh[4][wid] = d4; }
        __syncthreads();
        if (threadIdx.x < 5) {
            float t = 0.f;
            for (int w = 0; w < 8; w++) t += sh[threadIdx.x][w];
            float rr = 1.f / (1.f + expf(-(t + projb[0])));
            r[threadIdx.x] = rr;
            retain[(size_t)bn * (NL + 1) + threadIdx.x] = rr;
        }
        __syncthreads();
        const float r0 = r[0], r1 = r[1], r2 = r[2], r3 = r[3], r4 = r[4];
        for (int i = threadIdx.x; i < ND; i += 256)
            out[(size_t)bn * ND + i] = r0 * p0[i]
                + r1 * __half2float(p1[i]) + r2 * __half2float(p2[i])
                + r3 * __half2float(p3[i]) + r4 * __half2float(p4[i]);
        return;
    }
    const int rblk = blk - NB * NN;
    if (rblk < NB * 256) {
        const int b = rblk >> 8;
        const int mt = (rblk & 255) >> 4;
        const int nt = rblk & 15;
        __shared__ __half s[NL][32][33];
        const int tx = threadIdx.x & 31;
        const int ty8 = threadIdx.x >> 5;
#pragma unroll
        for (int l = 0; l < NL; l++)
#pragma unroll
            for (int r = 0; r < 32; r += 8) {
                int m = mt * 32 + ty8 + r;
                s[l][ty8 + r][tx] = g_aT16[l][(size_t)b * NN * NN + (size_t)m * NN + nt * 32 + tx];
            }
        __syncthreads();
#pragma unroll
        for (int r = 0; r < 32; r += 8) {
            int n = nt * 32 + ty8 + r;
            int m = mt * 32 + tx;
            float4 v = make_float4(
                __half2float(s[0][tx][ty8 + r]), __half2float(s[1][tx][ty8 + r]),
                __half2float(s[2][tx][ty8 + r]), __half2float(s[3][tx][ty8 + r]));
            ((float4*)adjs_out)[(size_t)(b * NN + n) * NN + m] = v;
        }
        return;
    }
    int t = threadIdx.x;
    if (t == 0) *o_l0 = g_l0 / ((g_fullsum + 1e-8f) * (float)NL);
    if (t < NB * NL) {
        int b = t / NL;
        float ps = g_psum[b];
        o_c[t] = g_cacc[t] / ps;
        o_g[t] = g_gacc[t] / (ps * ps);
    }
}

// ---------------- host orchestration ----------------
extern "C" void kernel_launch(void* const* d_in, const int* in_sizes, int n_in,
                              void* d_out, int out_size)
{
    (void)in_sizes; (void)n_in; (void)out_size;
    const float* pmask   = (const float*)d_in[0];
    const float* feature = (const float*)d_in[1];
    const float* Wq      = (const float*)d_in[2];
    const float* Wk      = (const float*)d_in[3];
    const float* projw   = (const float*)d_in[4];
    const float* projb   = (const float*)d_in[5];

    float* out    = (float*)d_out;
    float* retain = out + FS;
    float* adjs   = retain + (size_t)NB * NN * (NL + 1);
    float* o_l0   = adjs + AS * NL;
    float* o_c    = o_l0 + 1;
    float* o_g    = o_c + NB * NL;

    cudaFuncSetAttribute((const void*)&k_mma<0>, cudaFuncAttributeMaxDynamicSharedMemorySize, SMEM_BYTES);
    cudaFuncSetAttribute((const void*)&k_mma<1>, cudaFuncAttributeMaxDynamicSharedMemorySize, SMEM_BYTES);
    cudaFuncSetAttribute((const void*)&k_mma<2>, cudaFuncAttributeMaxDynamicSharedMemorySize, SMEM_BYTES);

    __half *paT16, *pF16, *pFp, *pWq16, *pWk16, *pMt, *pFt;
    cudaGetSymbolAddress((void**)&paT16, g_aT16);
    cudaGetSymbolAddress((void**)&pF16, g_F16);
    cudaGetSymbolAddress((void**)&pFp, g_Fp);
    cudaGetSymbolAddress((void**)&pWq16, g_Wq16);
    cudaGetSymbolAddress((void**)&pWk16, g_Wk16);
    cudaGetSymbolAddress((void**)&pMt, g_Mt);
    cudaGetSymbolAddress((void**)&pFt, g_Ft);

    {
        int cvt_blocks = ((int)(FS / 4) + 2 * (int)(NL * DD / 4) + 255) / 256;
        k_prep<<<288 + cvt_blocks, 256>>>(
            pmask, (const float4*)feature, (const float4*)Wq, (const float4*)Wk,
            (__half2*)pFp, (__half2*)pWq16, (__half2*)pWk16);
    }

    // Mt[l] = Wk[l] * Wq[l]^T (fp16), batched over layers
    k_mma<0><<<dim3(ND / BN, ND / BM, NL), 256, SMEM_BYTES>>>(
        pWk16, pWq16, pMt, ND, ND, ND, ND, DD, DD, DD, nullptr, 0);

    for (int l = 0; l < NL; l++) {
        const __half* Fsrc = (l == 0) ? pFp : pF16 + (size_t)(l - 1) * FS;
        // G = F * Mt[l]^T (fp16 into g_Ft scratch)
        k_mma<0><<<dim3(ND / BN, (NB * NN) / BM, 1), 256, SMEM_BYTES>>>(
            Fsrc, pMt + (size_t)l * DD, pFt,
            ND, ND, ND, ND, 0, 0, 0, nullptr, 0);
        // gate: adjT[l] fp16 only (+deg/c/g/l0)
        k_mma<1><<<dim3(NN / BN, NN / BM, NB), 256, SMEM_BYTES>>>(
            pFt, Fsrc, paT16 + (size_t)l * AS,
            ND, ND, ND, NN,
            (size_t)NN * ND, (size_t)NN * ND, (size_t)NN * NN, pmask, l);
        // Ft = (F * dis[n])^T fp16 (overwrites G scratch)
        t_ft<<<dim3(ND / 32, NN / 32, NB), dim3(32, 8)>>>(Fsrc, pFt, l);
        // Fnext[m,d] = dis[m] * sum_n adjT[m,n]*Ft[d,n]  (fp16, masked k-blocks skipped)
        k_mma<2><<<dim3(ND / BN, NN / BM, NB), 256, SMEM_BYTES>>>(
            paT16 + (size_t)l * AS, pFt, pF16 + (size_t)l * FS,
            NN, NN, NN, ND,
            (size_t)NN * NN, (size_t)ND * NN, (size_t)NN * ND, nullptr, l);
    }

    k_tail<<<NB * NN + NB * 256 + 1, 256>>>(
        feature, projw, projb, out, retain, adjs, o_l0, o_c, o_g);
}

// round 17
// speedup vs baseline: 1.3289x; 1.0642x over previous
#include <cuda_runtime.h>
#include <cuda_fp16.h>
#include <math.h>
#include <stdint.h>

#define NB 32
#define NN 512
#define ND 768
#define NL 4
#define FS ((size_t)NB * NN * ND)
#define AS ((size_t)NB * NN * NN)
#define DD ((size_t)ND * ND)
#define SCALE_LOGIT 0.03608439182435161f

#define BM 128
#define BN 128
#define BK 64
#define PP 72
#define SM_A 0
#define SM_B (BM * PP)
#define SM_STAGE ((BM + BN) * PP)        // 18432 halves
#define SMEM_BYTES (3 * SM_STAGE * 2)    // 110592 B
#define TPITCH 136

// prop kernel smem layout (B staged as [k][d] + dis)
#define PPB 136
#define PSM_A 0
#define PSM_B (BM * PP)                  // 9216
#define PSM_D (BM * PP + BK * PPB)       // 9216 + 8704 = 17920
#define PSM_STAGE (BM * PP + BK * PPB + BK)  // 17984 halves
#define PSMEM_BYTES (3 * PSM_STAGE * 2)      // 107904 B

// ---------------- static device scratch ----------------
__device__ __align__(16) __half g_aT16[NL][NB * NN * NN];
__device__ __align__(16) __half g_F16[NL][NB * NN * ND];
__device__ __align__(16) __half g_Fp[FS];
__device__ __align__(16) __half g_Wq16[NL * DD], g_Wk16[NL * DD];
__device__ __align__(16) __half g_Mt[NL * DD];
__device__ __align__(16) __half g_G[NB * NN * ND];
__device__ float g_deg[NL][NB * NN];
__device__ float g_psum[NB];
__device__ float g_fullsum, g_l0, g_cacc[NB * NL], g_gacc[NB * NL];

__device__ __forceinline__ float deg2dis(float d) {
    return (d > 0.f) ? rsqrtf(fmaxf(d, 1e-12f)) : 0.f;
}
__device__ __forceinline__ float fsig(float x) {
    return 1.f / (1.f + __expf(-x));
}

// ---------------- fused prep ----------------
__global__ void __launch_bounds__(256) k_prep(
    const float* __restrict__ pmask, const float4* __restrict__ f,
    const float4* __restrict__ wq, const float4* __restrict__ wk,
    __half2* __restrict__ hf, __half2* __restrict__ hwq, __half2* __restrict__ hwk)
{
    const int blk = blockIdx.x;
    if (blk < 256) {
        int i = blk * 256 + threadIdx.x;
        if (i < NL * NB * NN) ((float*)g_deg)[i] = 0.f;
        if (blk == 0) {
            if (threadIdx.x == 0) { g_l0 = 0.f; g_fullsum = 0.f; }
            if (threadIdx.x < NB * NL) { g_cacc[threadIdx.x] = 0.f; g_gacc[threadIdx.x] = 0.f; }
        }
        return;
    }
    if (blk < 288) {
        int b = blk - 256;
        float s = 0.f;
        for (int i = threadIdx.x; i < NN; i += 256) s += pmask[b * NN + i];
#pragma unroll
        for (int o = 16; o; o >>= 1) s += __shfl_xor_sync(0xffffffffu, s, o);
        __shared__ float sh[8];
        if ((threadIdx.x & 31) == 0) sh[threadIdx.x >> 5] = s;
        __syncthreads();
        if (threadIdx.x == 0) {
            float t = 0.f;
            for (int w = 0; w < 8; w++) t += sh[w];
            g_psum[b] = t;
            atomicAdd(&g_fullsum, t * t);
        }
        return;
    }
    const int NF = (int)(FS / 4), NW = (int)(NL * DD / 4);
    int i = (blk - 288) * 256 + threadIdx.x;
    const float4* src;
    __half2* dst;
    int j;
    if (i < NF) { src = f; dst = hf; j = i; }
    else if (i < NF + NW) { src = wq; dst = hwq; j = i - NF; }
    else if (i < NF + 2 * NW) { src = wk; dst = hwk; j = i - NF - NW; }
    else return;
    float4 v = src[j];
    dst[2 * j]     = __floats2half2_rn(v.x, v.y);
    dst[2 * j + 1] = __floats2half2_rn(v.z, v.w);
}

// ---------------- common PTX helpers ----------------
__device__ __forceinline__ void mma16816(float* d, const uint32_t* a, uint32_t b0, uint32_t b1) {
    asm volatile(
        "mma.sync.aligned.m16n8k16.row.col.f32.f16.f16.f32 "
        "{%0,%1,%2,%3},{%4,%5,%6,%7},{%8,%9},{%0,%1,%2,%3};\n"
        : "+f"(d[0]), "+f"(d[1]), "+f"(d[2]), "+f"(d[3])
        : "r"(a[0]), "r"(a[1]), "r"(a[2]), "r"(a[3]), "r"(b0), "r"(b1));
}
__device__ __forceinline__ void ldsm4(uint32_t& d0, uint32_t& d1, uint32_t& d2, uint32_t& d3,
                                      uint32_t addr) {
    asm volatile("ldmatrix.sync.aligned.m8n8.x4.shared.b16 {%0,%1,%2,%3}, [%4];\n"
                 : "=r"(d0), "=r"(d1), "=r"(d2), "=r"(d3) : "r"(addr));
}
__device__ __forceinline__ void ldsm4t(uint32_t& d0, uint32_t& d1, uint32_t& d2, uint32_t& d3,
                                       uint32_t addr) {
    asm volatile("ldmatrix.sync.aligned.m8n8.x4.trans.shared.b16 {%0,%1,%2,%3}, [%4];\n"
                 : "=r"(d0), "=r"(d1), "=r"(d2), "=r"(d3) : "r"(addr));
}
__device__ __forceinline__ void cpa16(__half* dst, const __half* src) {
    uint32_t d = (uint32_t)__cvta_generic_to_shared(dst);
    asm volatile("cp.async.cg.shared.global [%0], [%1], 16;\n" :: "r"(d), "l"(src));
}

// ---------------- NT GEMM: EPI 0 = fp16 store, 1 = gate ----------------
template <int EPI>
__global__ void __launch_bounds__(256, 2) k_mma(
    const __half* __restrict__ Ag, const __half* __restrict__ Bg,
    __half* __restrict__ O,
    int K, int lda, int ldb, int ldc,
    size_t bsA, size_t bsB, size_t bsO,
    const float* __restrict__ pmask, int layer)
{
    extern __shared__ __align__(16) __half smem[];
    __shared__ float pmr[BM], pmc[BN];
    __shared__ float red[3][8];

    const int bz = blockIdx.z;
    Ag += bz * bsA; Bg += bz * bsB;
    O += bz * bsO;

    const int tid = threadIdx.x;
    const int m0 = blockIdx.y * BM;
    const int n0 = blockIdx.x * BN;

    if (EPI == 1) {
        if (tid < BM) pmr[tid] = pmask[bz * NN + m0 + tid];
        else          pmc[tid - BM] = pmask[bz * NN + n0 + (tid - BM)];
    }

    auto load_stage = [&](int s, int k0) {
        __half* dst = smem + s * SM_STAGE;
#pragma unroll
        for (int i = 0; i < 4; i++) {
            int q = i * 256 + tid, row = q >> 3, c = q & 7;
            cpa16(dst + SM_A + row * PP + c * 8, Ag + (size_t)(m0 + row) * lda + k0 + c * 8);
        }
#pragma unroll
        for (int i = 0; i < 4; i++) {
            int q = i * 256 + tid, row = q >> 3, c = q & 7;
            cpa16(dst + SM_B + row * PP + c * 8, Bg + (size_t)(n0 + row) * ldb + k0 + c * 8);
        }
        asm volatile("cp.async.commit_group;\n");
    };

    float acc[2][8][4];
#pragma unroll
    for (int mi = 0; mi < 2; mi++)
#pragma unroll
        for (int nj = 0; nj < 8; nj++)
#pragma unroll
            for (int q = 0; q < 4; q++) acc[mi][nj][q] = 0.f;

    const int lane = tid & 31;
    const int wid = tid >> 5;
    const int g = lane >> 2, t4 = lane & 3;
    const int wr = (wid & 3) * 32;
    const int wc = (wid >> 2) * 64;

    const uint32_t smem32 = (uint32_t)__cvta_generic_to_shared(smem);
    const int aRow = wr + (lane & 15);
    const int aKof = (lane >> 4) << 3;
    const int bRow = wc + (lane & 7) + ((lane >> 4) << 3);
    const int bKof = ((lane >> 3) & 1) << 3;

    const int KT = K / BK;
    load_stage(0, 0);
    load_stage(1, BK);

    for (int kt = 0; kt < KT; kt++) {
        int s = kt % 3;
        if (kt + 1 < KT) {
            asm volatile("cp.async.wait_group 1;\n");
        } else {
            asm volatile("cp.async.wait_group 0;\n");
        }
        __syncthreads();
        if (kt + 2 < KT) load_stage((kt + 2) % 3, (kt + 2) * BK);

        const uint32_t sA32 = smem32 + (s * SM_STAGE + SM_A) * 2;
        const uint32_t sB32 = smem32 + (s * SM_STAGE + SM_B) * 2;

#pragma unroll
        for (int kk = 0; kk < BK; kk += 16) {
            uint32_t af[2][4], bf[8][2];
#pragma unroll
            for (int mi = 0; mi < 2; mi++)
                ldsm4(af[mi][0], af[mi][1], af[mi][2], af[mi][3],
                      sA32 + ((aRow + 16 * mi) * PP + kk + aKof) * 2);
#pragma unroll
            for (int j = 0; j < 4; j++)
                ldsm4(bf[2 * j][0], bf[2 * j][1], bf[2 * j + 1][0], bf[2 * j + 1][1],
                      sB32 + ((bRow + 16 * j) * PP + kk + bKof) * 2);
#pragma unroll
            for (int nj = 0; nj < 8; nj++)
#pragma unroll
                for (int mi = 0; mi < 2; mi++)
                    mma16816(acc[mi][nj], af[mi], bf[nj][0], bf[nj][1]);
        }
    }

    // ---------------- epilogues ----------------
    if (EPI == 0) {
#pragma unroll
        for (int mi = 0; mi < 2; mi++) {
            const int R = m0 + wr + 16 * mi + g;
#pragma unroll
            for (int nj = 0; nj < 8; nj++) {
                const int Cc = n0 + wc + 8 * nj + 2 * t4;
                *(__half2*)(O + (size_t)R * ldc + Cc) =
                    __floats2half2_rn(acc[mi][nj][0], acc[mi][nj][1]);
                *(__half2*)(O + (size_t)(R + 8) * ldc + Cc) =
                    __floats2half2_rn(acc[mi][nj][2], acc[mi][nj][3]);
            }
        }
    } else {  // gate: adjT only
        __syncthreads();
        __half* tb = smem;
        const bool edge = (m0 + BM >= NN) || (n0 + BN >= NN);
        float l0loc = 0.f, cloc = 0.f, gloc = 0.f;
#pragma unroll
        for (int mi = 0; mi < 2; mi++) {
            const int Rl = wr + 16 * mi + g;
            const int R = m0 + Rl;
            const float pr1 = pmr[Rl], pr2 = pmr[Rl + 8];
            float row1 = 0.f, row2 = 0.f;
#pragma unroll
            for (int nj = 0; nj < 8; nj++) {
                const int Ccl = wc + 8 * nj + 2 * t4;
                const int Cc = n0 + Ccl;
                const float pc0 = pmc[Ccl], pc1 = pmc[Ccl + 1];
                float v00 = fsig(acc[mi][nj][0] * SCALE_LOGIT) * pr1 * pc0;
                float v01 = fsig(acc[mi][nj][1] * SCALE_LOGIT) * pr1 * pc1;
                float v10 = fsig(acc[mi][nj][2] * SCALE_LOGIT) * pr2 * pc0;
                float v11 = fsig(acc[mi][nj][3] * SCALE_LOGIT) * pr2 * pc1;
                row1 += v00 + v01;
                row2 += v10 + v11;
                l0loc += v00 + v01 + v10 + v11;
                if (edge) {
                    const bool c0ok = (Cc < NN - 1), c1ok = (Cc + 1 < NN - 1);
                    float e1 = (c0ok ? v00 : 0.f) + (c1ok ? v01 : 0.f);
                    float e2 = (c0ok ? v10 : 0.f) + (c1ok ? v11 : 0.f);
                    if (R == NN - 1) cloc += e1; else gloc += e1;
                    if (R + 8 == NN - 1) cloc += e2; else gloc += e2;
                }
                __half2 h1 = __floats2half2_rn(v00, v01);
                __half2 h2 = __floats2half2_rn(v10, v11);
                tb[Ccl * TPITCH + Rl]           = __low2half(h1);
                tb[(Ccl + 1) * TPITCH + Rl]     = __high2half(h1);
                tb[Ccl * TPITCH + Rl + 8]       = __low2half(h2);
                tb[(Ccl + 1) * TPITCH + Rl + 8] = __high2half(h2);
            }
            row1 += __shfl_xor_sync(0xffffffffu, row1, 1);
            row1 += __shfl_xor_sync(0xffffffffu, row1, 2);
            row2 += __shfl_xor_sync(0xffffffffu, row2, 1);
            row2 += __shfl_xor_sync(0xffffffffu, row2, 2);
            if (t4 == 0) {
                atomicAdd(&g_deg[layer][bz * NN + R], row1);
                atomicAdd(&g_deg[layer][bz * NN + R + 8], row2);
            }
        }
        if (!edge) gloc = l0loc;
        __syncthreads();
        for (int e2 = tid; e2 < BN * (BM / 2); e2 += 256) {
            int row = e2 >> 6, col2 = e2 & 63;
            uint32_t v = *(const uint32_t*)&tb[row * TPITCH + 2 * col2];
            *(uint32_t*)(O + (size_t)(n0 + row) * NN + m0 + 2 * col2) = v;
        }
#pragma unroll
        for (int o = 16; o; o >>= 1) {
            l0loc += __shfl_xor_sync(0xffffffffu, l0loc, o);
            cloc  += __shfl_xor_sync(0xffffffffu, cloc, o);
            gloc  += __shfl_xor_sync(0xffffffffu, gloc, o);
        }
        if (lane == 0) { red[0][wid] = l0loc; red[1][wid] = cloc; red[2][wid] = gloc; }
        __syncthreads();
        if (tid == 0) {
            float a = 0.f, c = 0.f, gg = 0.f;
            for (int w = 0; w < 8; w++) { a += red[0][w]; c += red[1][w]; gg += red[2][w]; }
            atomicAdd(&g_l0, a);
            atomicAdd(&g_cacc[bz * NL + layer], c);
            atomicAdd(&g_gacc[bz * NL + layer], gg);
        }
    }
}

// ---------------- prop: Fnext[m,d] = dis[m] * sum_n adjT[m,n]*dis[n]*F[n,d] ----------------
// B read directly from F[n][d] via ldmatrix.trans; dis[n] folded into b-fragments;
// k-block skip over masked n (valid n = [0,len) U {511}).
__global__ void __launch_bounds__(256, 2) k_prop(
    const __half* __restrict__ Ag, const __half* __restrict__ Fg,
    __half* __restrict__ O, int layer)
{
    extern __shared__ __align__(16) __half smem[];
    const int bz = blockIdx.z;
    Ag += (size_t)bz * NN * NN;
    Fg += (size_t)bz * NN * ND;
    O  += (size_t)bz * NN * ND;

    const int tid = threadIdx.x;
    const int m0 = blockIdx.y * BM;
    const int d0 = blockIdx.x * BN;

    auto load_stage = [&](int s, int k0) {
        __half* dst = smem + s * PSM_STAGE;
#pragma unroll
        for (int i = 0; i < 4; i++) {       // A: 128 rows x 64 k
            int q = i * 256 + tid, row = q >> 3, c = q & 7;
            cpa16(dst + PSM_A + row * PP + c * 8, Ag + (size_t)(m0 + row) * NN + k0 + c * 8);
        }
#pragma unroll
        for (int i = 0; i < 4; i++) {       // B: 64 rows (k=n) x 128 cols (d)
            int q = i * 256 + tid, row = q >> 4, c = q & 15;
            cpa16(dst + PSM_B + row * PPB + c * 8, Fg + (size_t)(k0 + row) * ND + d0 + c * 8);
        }
        asm volatile("cp.async.commit_group;\n");
        if (tid < BK)
            dst[PSM_D + tid] = __float2half(deg2dis(g_deg[layer][bz * NN + k0 + tid]));
    };

    float acc[2][8][4];
#pragma unroll
    for (int mi = 0; mi < 2; mi++)
#pragma unroll
        for (int nj = 0; nj < 8; nj++)
#pragma unroll
            for (int q = 0; q < 4; q++) acc[mi][nj][q] = 0.f;

    const int lane = tid & 31;
    const int wid = tid >> 5;
    const int g = lane >> 2, t4 = lane & 3;
    const int wr = (wid & 3) * 32;
    const int wc = (wid >> 2) * 64;

    const uint32_t smem32 = (uint32_t)__cvta_generic_to_shared(smem);
    const int aRow = wr + (lane & 15);
    const int aKof = (lane >> 4) << 3;
    const int bkRow = lane & 15;            // k row for trans ldsm
    const int bCol = (lane >> 4) << 3;      // 0 or 8 within n16 block

    // k-block schedule: skip blocks covering only masked-out n
    int len = (int)(g_psum[bz] + 0.5f) - 1;
    int Cv = (len + BK - 1) / BK;
    const int NBK = NN / BK;
    int KT = (Cv >= NBK) ? NBK : (Cv + 1);
    const int LASTB = NBK - 1;
#define KBLK(i) (((i) >= Cv) ? LASTB : (i))

    load_stage(0, KBLK(0) * BK);
    load_stage(1, KBLK(1) * BK);

    for (int kt = 0; kt < KT; kt++) {
        int s = kt % 3;
        if (kt + 1 < KT) {
            asm volatile("cp.async.wait_group 1;\n");
        } else {
            asm volatile("cp.async.wait_group 0;\n");
        }
        __syncthreads();
        if (kt + 2 < KT) load_stage((kt + 2) % 3, KBLK(kt + 2) * BK);

        const uint32_t sA32 = smem32 + (s * PSM_STAGE + PSM_A) * 2;
        const uint32_t sB32 = smem32 + (s * PSM_STAGE + PSM_B) * 2;
        const __half* sdis = smem + s * PSM_STAGE + PSM_D;

#pragma unroll
        for (int kk = 0; kk < BK; kk += 16) {
            uint32_t af[2][4], bf[8][2];
#pragma unroll
            for (int mi = 0; mi < 2; mi++)
                ldsm4(af[mi][0], af[mi][1], af[mi][2], af[mi][3],
                      sA32 + ((aRow + 16 * mi) * PP + kk + aKof) * 2);
#pragma unroll
            for (int j = 0; j < 4; j++)
                ldsm4t(bf[2 * j][0], bf[2 * j][1], bf[2 * j + 1][0], bf[2 * j + 1][1],
                       sB32 + ((kk + bkRow) * PPB + wc + 16 * j + bCol) * 2);
            // fold dis[n] into b-fragments: reg0 holds k=2t4,2t4+1; reg1 holds k=8+2t4,+1
            const __half2 q0 = *reinterpret_cast<const __half2*>(sdis + kk + 2 * t4);
            const __half2 q1 = *reinterpret_cast<const __half2*>(sdis + kk + 8 + 2 * t4);
#pragma unroll
            for (int nj = 0; nj < 8; nj++) {
                __half2 b0 = __hmul2(*reinterpret_cast<__half2*>(&bf[nj][0]), q0);
                __half2 b1 = __hmul2(*reinterpret_cast<__half2*>(&bf[nj][1]), q1);
                bf[nj][0] = *reinterpret_cast<uint32_t*>(&b0);
                bf[nj][1] = *reinterpret_cast<uint32_t*>(&b1);
            }
#pragma unroll
            for (int nj = 0; nj < 8; nj++)
#pragma unroll
                for (int mi = 0; mi < 2; mi++)
                    mma16816(acc[mi][nj], af[mi], bf[nj][0], bf[nj][1]);
        }
    }
#undef KBLK

    // epilogue: row scale by dis[m], fp16 store
#pragma unroll
    for (int mi = 0; mi < 2; mi++) {
        const int R = m0 + wr + 16 * mi + g;
        const float s1 = deg2dis(g_deg[layer][bz * NN + R]);
        const float s2 = deg2dis(g_deg[layer][bz * NN + R + 8]);
#pragma unroll
        for (int nj = 0; nj < 8; nj++) {
            const int Cc = d0 + wc + 8 * nj + 2 * t4;
            *(__half2*)(O + (size_t)R * ND + Cc) =
                __floats2half2_rn(acc[mi][nj][0] * s1, acc[mi][nj][1] * s1);
            *(__half2*)(O + (size_t)(R + 8) * ND + Cc) =
                __floats2half2_rn(acc[mi][nj][2] * s2, acc[mi][nj][3] * s2);
        }
    }
}

// ---------------- fused tail: attention-pool + transposed repack + finalize ----------------
__global__ void __launch_bounds__(256) k_tail(
    const float* __restrict__ F0, const float* __restrict__ projw,
    const float* __restrict__ projb, float* __restrict__ out, float* __restrict__ retain,
    float* __restrict__ adjs_out,
    float* __restrict__ o_l0, float* __restrict__ o_c, float* __restrict__ o_g)
{
    const int blk = blockIdx.x;
    if (blk < NB * NN) {
        const int bn = blk;
        const float* p0 = F0 + (size_t)bn * ND;
        const __half* p1 = g_F16[0] + (size_t)bn * ND;
        const __half* p2 = g_F16[1] + (size_t)bn * ND;
        const __half* p3 = g_F16[2] + (size_t)bn * ND;
        const __half* p4 = g_F16[3] + (size_t)bn * ND;
        float d0 = 0.f, d1 = 0.f, d2 = 0.f, d3 = 0.f, d4 = 0.f;
        for (int i = threadIdx.x; i < ND; i += 256) {
            float w = projw[i];
            d0 += p0[i] * w;
            d1 += __half2float(p1[i]) * w;
            d2 += __half2float(p2[i]) * w;
            d3 += __half2float(p3[i]) * w;
            d4 += __half2float(p4[i]) * w;
        }
#pragma unroll
        for (int o = 16; o; o >>= 1) {
            d0 += __shfl_xor_sync(0xffffffffu, d0, o);
            d1 += __shfl_xor_sync(0xffffffffu, d1, o);
            d2 += __shfl_xor_sync(0xffffffffu, d2, o);
            d3 += __shfl_xor_sync(0xffffffffu, d3, o);
            d4 += __shfl_xor_sync(0xffffffffu, d4, o);
        }
        __shared__ float sh[5][8], r[5];
        const int wid = threadIdx.x >> 5, lane = threadIdx.x & 31;
        if (lane == 0) { sh[0][wid] = d0; sh[1][wid] = d1; sh[2][wid] = d2; sh[3][wid] = d3; sh[4][wid] = d4; }
        __syncthreads();
        if (threadIdx.x < 5) {
            float t = 0.f;
            for (int w = 0; w < 8; w++) t += sh[threadIdx.x][w];
            float rr = 1.f / (1.f + expf(-(t + projb[0])));
            r[threadIdx.x] = rr;
            retain[(size_t)bn * (NL + 1) + threadIdx.x] = rr;
        }
        __syncthreads();
        const float r0 = r[0], r1 = r[1], r2 = r[2], r3 = r[3], r4 = r[4];
        for (int i = threadIdx.x; i < ND; i += 256)
            out[(size_t)bn * ND + i] = r0 * p0[i]
                + r1 * __half2float(p1[i]) + r2 * __half2float(p2[i])
                + r3 * __half2float(p3[i]) + r4 * __half2float(p4[i]);
        return;
    }
    const int rblk = blk - NB * NN;
    if (rblk < NB * 256) {
        const int b = rblk >> 8;
        const int mt = (rblk & 255) >> 4;
        const int nt = rblk & 15;
        __shared__ __half s[NL][32][33];
        const int tx = threadIdx.x & 31;
        const int ty8 = threadIdx.x >> 5;
#pragma unroll
        for (int l = 0; l < NL; l++)
#pragma unroll
            for (int r = 0; r < 32; r += 8) {
                int m = mt * 32 + ty8 + r;
                s[l][ty8 + r][tx] = g_aT16[l][(size_t)b * NN * NN + (size_t)m * NN + nt * 32 + tx];
            }
        __syncthreads();
#pragma unroll
        for (int r = 0; r < 32; r += 8) {
            int n = nt * 32 + ty8 + r;
            int m = mt * 32 + tx;
            float4 v = make_float4(
                __half2float(s[0][tx][ty8 + r]), __half2float(s[1][tx][ty8 + r]),
                __half2float(s[2][tx][ty8 + r]), __half2float(s[3][tx][ty8 + r]));
            ((float4*)adjs_out)[(size_t)(b * NN + n) * NN + m] = v;
        }
        return;
    }
    int t = threadIdx.x;
    if (t == 0) *o_l0 = g_l0 / ((g_fullsum + 1e-8f) * (float)NL);
    if (t < NB * NL) {
        int b = t / NL;
        float ps = g_psum[b];
        o_c[t] = g_cacc[t] / ps;
        o_g[t] = g_gacc[t] / (ps * ps);
    }
}

// ---------------- host orchestration ----------------
extern "C" void kernel_launch(void* const* d_in, const int* in_sizes, int n_in,
                              void* d_out, int out_size)
{
    (void)in_sizes; (void)n_in; (void)out_size;
    const float* pmask   = (const float*)d_in[0];
    const float* feature = (const float*)d_in[1];
    const float* Wq      = (const float*)d_in[2];
    const float* Wk      = (const float*)d_in[3];
    const float* projw   = (const float*)d_in[4];
    const float* projb   = (const float*)d_in[5];

    float* out    = (float*)d_out;
    float* retain = out + FS;
    float* adjs   = retain + (size_t)NB * NN * (NL + 1);
    float* o_l0   = adjs + AS * NL;
    float* o_c    = o_l0 + 1;
    float* o_g    = o_c + NB * NL;

    cudaFuncSetAttribute((const void*)&k_mma<0>, cudaFuncAttributeMaxDynamicSharedMemorySize, SMEM_BYTES);
    cudaFuncSetAttribute((const void*)&k_mma<1>, cudaFuncAttributeMaxDynamicSharedMemorySize, SMEM_BYTES);
    cudaFuncSetAttribute((const void*)&k_prop, cudaFuncAttributeMaxDynamicSharedMemorySize, PSMEM_BYTES);

    __half *paT16, *pF16, *pFp, *pWq16, *pWk16, *pMt, *pG;
    cudaGetSymbolAddress((void**)&paT16, g_aT16);
    cudaGetSymbolAddress((void**)&pF16, g_F16);
    cudaGetSymbolAddress((void**)&pFp, g_Fp);
    cudaGetSymbolAddress((void**)&pWq16, g_Wq16);
    cudaGetSymbolAddress((void**)&pWk16, g_Wk16);
    cudaGetSymbolAddress((void**)&pMt, g_Mt);
    cudaGetSymbolAddress((void**)&pG, g_G);

    {
        int cvt_blocks = ((int)(FS / 4) + 2 * (int)(NL * DD / 4) + 255) / 256;
        k_prep<<<288 + cvt_blocks, 256>>>(
            pmask, (const float4*)feature, (const float4*)Wq, (const float4*)Wk,
            (__half2*)pFp, (__half2*)pWq16, (__half2*)pWk16);
    }

    // Mt[l] = Wk[l] * Wq[l]^T (fp16), batched over layers
    k_mma<0><<<dim3(ND / BN, ND / BM, NL), 256, SMEM_BYTES>>>(
        pWk16, pWq16, pMt, ND, ND, ND, ND, DD, DD, DD, nullptr, 0);

    for (int l = 0; l < NL; l++) {
        const __half* Fsrc = (l == 0) ? pFp : pF16 + (size_t)(l - 1) * FS;
        // G = F * Mt[l]^T (fp16)
        k_mma<0><<<dim3(ND / BN, (NB * NN) / BM, 1), 256, SMEM_BYTES>>>(
            Fsrc, pMt + (size_t)l * DD, pG,
            ND, ND, ND, ND, 0, 0, 0, nullptr, 0);
        // gate: adjT[l] fp16 (+deg/c/g/l0)
        k_mma<1><<<dim3(NN / BN, NN / BM, NB), 256, SMEM_BYTES>>>(
            pG, Fsrc, paT16 + (size_t)l * AS,
            ND, ND, ND, NN,
            (size_t)NN * ND, (size_t)NN * ND, (size_t)NN * NN, pmask, l);
        // prop: Fnext = dis[m] * adjT * (dis[n] * F), B read from F directly
        k_prop<<<dim3(ND / BN, NN / BM, NB), 256, PSMEM_BYTES>>>(
            paT16 + (size_t)l * AS, Fsrc, pF16 + (size_t)l * FS, l);
    }

    k_tail<<<NB * NN + NB * 256 + 1, 256>>>(
        feature, projw, projb, out, retain, adjs, o_l0, o_c, o_g);
}